// round 12
// baseline (speedup 1.0000x reference)
#include <cuda_runtime.h>
#include <cuda_bf16.h>
#include <cuda_fp16.h>
#include <math.h>
#include <stdint.h>

// Problem constants
#define LL 13
#define HH 48
#define WW 96
#define DD 512
#define TT (LL*HH*WW)        // 59904 tokens
#define NHEAD 16
#define HD 32

// Scratch (device globals; no cudaMalloc allowed)
__device__ __half g_lnh[(size_t)TT * DD];          // LN output (GEMM A), f16
__device__ __half g_qkvh[(size_t)TT * 3 * DD];     // QKV output, f16
__device__ __half g_atth[(size_t)TT * DD];         // attention output (proj A), f16
__device__ float  g_state[(size_t)TT * DD];        // residual stream, fp32
__device__ float  g_sin_lat[HH * 16];
__device__ float  g_cos_lat[HH * 16];
__device__ float  g_sin_lon[WW * 16];
__device__ float  g_cos_lon[WW * 16];
__device__ uint32_t g_wp_qkv[3][(DD / 2) * 3 * DD];  // packed f16 weights [K/2][N]
__device__ uint32_t g_wp_proj[(DD / 2) * DD];

// ---------------------------------------------------------------------------
// MMA + helpers
// ---------------------------------------------------------------------------
__device__ __forceinline__ void mma_f16(float* d, const uint32_t* a, const uint32_t* b)
{
    asm volatile(
        "mma.sync.aligned.m16n8k16.row.col.f32.f16.f16.f32 "
        "{%0,%1,%2,%3}, {%4,%5,%6,%7}, {%8,%9}, {%0,%1,%2,%3};"
        : "+f"(d[0]), "+f"(d[1]), "+f"(d[2]), "+f"(d[3])
        : "r"(a[0]), "r"(a[1]), "r"(a[2]), "r"(a[3]), "r"(b[0]), "r"(b[1]));
}

__device__ __forceinline__ uint32_t pack_h2(float lo, float hi)
{
    __half2 t = __floats2half2_rn(lo, hi);
    return *(uint32_t*)&t;
}

__device__ __forceinline__ void cp_async16(uint32_t dst, const void* src)
{
    asm volatile("cp.async.cg.shared.global [%0], [%1], 16;\n" :: "r"(dst), "l"(src));
}
__device__ __forceinline__ void cp_commit()
{
    asm volatile("cp.async.commit_group;\n" ::: "memory");
}
__device__ __forceinline__ void cp_wait0()
{
    asm volatile("cp.async.wait_group 0;\n" ::: "memory");
}

// ---------------------------------------------------------------------------
// Weight pack: W[K][N] fp32 -> out[k2][n] = half2(W[2k2][n], W[2k2+1][n])
// ---------------------------------------------------------------------------
__global__ void pack_w_kernel(const float* __restrict__ W, uint32_t* __restrict__ out,
                              int K, int N)
{
    int n  = blockIdx.x * 256 + threadIdx.x;
    int k2 = blockIdx.y;
    if (n < N)
        out[(size_t)k2 * N + n] =
            pack_h2(W[(size_t)(2 * k2) * N + n], W[(size_t)(2 * k2 + 1) * N + n]);
}

// ---------------------------------------------------------------------------
// Rotary sin/cos precompute. mode 0: lat axis (lon=0), mode 1: lon axis (lat=0)
// ---------------------------------------------------------------------------
__global__ void rotary_kernel(const float* __restrict__ grid, int S, int mode,
                              float* __restrict__ sout, float* __restrict__ cout)
{
    int idx = blockIdx.x * blockDim.x + threadIdx.x;
    if (idx >= S * 16) return;
    int s = idx >> 4;
    int f = idx & 15;
    const float PI = 3.14159265358979323846f;
    float lat, lon;
    if (mode == 0) { lat = grid[s]; lon = 0.f; }
    else           { lat = 0.f;     lon = grid[s]; }
    float two_pi = 2.f * PI;
    float r = fmodf(lon + PI, two_pi);
    if (r < 0.f) r += two_pi;
    float lonw = r - PI;
    float lo = -(PI * 0.5f) + 1e-6f;
    float hi =  (PI * 0.5f) - 1e-6f;
    float latc = fminf(fmaxf(lat, lo), hi);
    float invf = powf(10000.f, -(float)f / 16.f);
    float phase = (latc + lonw * cosf(latc)) * invf;
    sout[idx] = sinf(phase);
    cout[idx] = cosf(phase);
}

// ---------------------------------------------------------------------------
// LayerNorm, warp-per-token (no smem, no block barriers). 256 thr = 8 tokens.
// ---------------------------------------------------------------------------
__global__ void ln_kernel(const float* __restrict__ x, const float* __restrict__ g,
                          const float* __restrict__ b, __half* __restrict__ out)
{
    int warp = threadIdx.x >> 5, lane = threadIdx.x & 31;
    int t = blockIdx.x * 8 + warp;
    const float* row = x + (size_t)t * DD;

    float4 v[4];
    float s = 0.f, q = 0.f;
    #pragma unroll
    for (int k = 0; k < 4; k++) {
        v[k] = *(const float4*)(row + lane * 4 + 128 * k);
        s += v[k].x + v[k].y + v[k].z + v[k].w;
        q += v[k].x*v[k].x + v[k].y*v[k].y + v[k].z*v[k].z + v[k].w*v[k].w;
    }
    #pragma unroll
    for (int o = 16; o; o >>= 1) {
        s += __shfl_xor_sync(0xffffffffu, s, o);
        q += __shfl_xor_sync(0xffffffffu, q, o);
    }
    float mean = s * (1.f / 512.f);
    float var  = q * (1.f / 512.f) - mean * mean;
    float inv = rsqrtf(var + 1e-5f);

    #pragma unroll
    for (int k = 0; k < 4; k++) {
        float4 gv = *(const float4*)(g + lane * 4 + 128 * k);
        float4 bv = *(const float4*)(b + lane * 4 + 128 * k);
        uint2 o;
        o.x = pack_h2((v[k].x - mean) * inv * gv.x + bv.x,
                      (v[k].y - mean) * inv * gv.y + bv.y);
        o.y = pack_h2((v[k].z - mean) * inv * gv.z + bv.z,
                      (v[k].w - mean) * inv * gv.w + bv.w);
        *(uint2*)(out + (size_t)t * DD + lane * 4 + 128 * k) = o;
    }
}

// ---------------------------------------------------------------------------
// F16 tensor-core GEMM (round-8 proven structure): C = A@B + bias (+ res)
// ---------------------------------------------------------------------------
__device__ __forceinline__ void gemm_issue_chunk(
    const __half* __restrict__ A, const uint32_t* __restrict__ Bp,
    int N, int K, int m0, int n0, int tid,
    uint32_t as_base, uint32_t bs_base,
    int chunk, int buf)
{
    int k0 = chunk * 32;
    int arow = tid >> 2;
    int aq   = tid & 3;
    #pragma unroll
    for (int i = 0; i < 4; i++) {
        int row = arow + 32 * i;
        uint32_t dst = as_base + (uint32_t)(((buf * 128 + row) * 20 + aq * 4) * 4);
        cp_async16(dst, A + (size_t)(m0 + row) * K + k0 + aq * 8);
    }
    int bk = tid >> 5;
    int bt = tid & 31;
    #pragma unroll
    for (int i = 0; i < 4; i++) {
        int krow = bk + 4 * i;
        uint32_t dst = bs_base + (uint32_t)(((buf * 16 + krow) * 136 + bt * 4) * 4);
        cp_async16(dst, Bp + (size_t)(k0 / 2 + krow) * N + n0 + bt * 4);
    }
    cp_commit();
}

template<typename OutT>
__global__ __launch_bounds__(128) void gemm_f16_kernel(
    const __half* __restrict__ A, const uint32_t* __restrict__ Bp,
    const float* __restrict__ bias, const float* __restrict__ res,
    OutT* __restrict__ C, int M, int N, int K)
{
    __shared__ uint32_t Au[2][128][20];
    __shared__ uint32_t Bu[2][16][136];

    int tid  = threadIdx.x;
    int lane = tid & 31;
    int warp = tid >> 5;
    int wm   = warp >> 1;
    int wn   = warp & 1;
    int r    = lane >> 2;
    int c    = lane & 3;

    int m0 = blockIdx.y * 128;
    int n0 = blockIdx.x * 128;

    uint32_t as_base = (uint32_t)__cvta_generic_to_shared(&Au[0][0][0]);
    uint32_t bs_base = (uint32_t)__cvta_generic_to_shared(&Bu[0][0][0]);

    float acc[4][8][4];
    #pragma unroll
    for (int i = 0; i < 4; i++)
        #pragma unroll
        for (int j = 0; j < 8; j++)
            #pragma unroll
            for (int e = 0; e < 4; e++) acc[i][j][e] = 0.f;

    const int NCHUNK = K / 32;

    gemm_issue_chunk(A, Bp, N, K, m0, n0, tid, as_base, bs_base, 0, 0);

    for (int chunk = 0; chunk < NCHUNK; chunk++) {
        int buf = chunk & 1;
        cp_wait0();
        __syncthreads();

        if (chunk + 1 < NCHUNK)
            gemm_issue_chunk(A, Bp, N, K, m0, n0, tid,
                             as_base, bs_base, chunk + 1, buf ^ 1);

        #pragma unroll
        for (int ks = 0; ks < 2; ks++) {
            int kb = ks * 8;
            uint32_t afrag[4][4];
            #pragma unroll
            for (int i = 0; i < 4; i++) {
                int row = wm * 64 + i * 16 + r;
                afrag[i][0] = Au[buf][row][kb + c];
                afrag[i][1] = Au[buf][row + 8][kb + c];
                afrag[i][2] = Au[buf][row][kb + c + 4];
                afrag[i][3] = Au[buf][row + 8][kb + c + 4];
            }
            uint32_t bfrag[8][2];
            #pragma unroll
            for (int j = 0; j < 8; j++) {
                int col = wn * 64 + j * 8 + r;
                bfrag[j][0] = Bu[buf][kb + c][col];
                bfrag[j][1] = Bu[buf][kb + c + 4][col];
            }
            #pragma unroll
            for (int i = 0; i < 4; i++)
                #pragma unroll
                for (int j = 0; j < 8; j++)
                    mma_f16(acc[i][j], afrag[i], bfrag[j]);
        }
        __syncthreads();
    }

    #pragma unroll
    for (int i = 0; i < 4; i++) {
        int row0 = m0 + wm * 64 + i * 16 + r;
        #pragma unroll
        for (int j = 0; j < 8; j++) {
            int col = n0 + wn * 64 + j * 8 + 2 * c;
            float bv0 = bias[col];
            float bv1 = bias[col + 1];
            size_t idx0 = (size_t)row0 * N + col;
            size_t idx1 = (size_t)(row0 + 8) * N + col;
            float o00 = acc[i][j][0] + bv0, o01 = acc[i][j][1] + bv1;
            float o10 = acc[i][j][2] + bv0, o11 = acc[i][j][3] + bv1;
            if (res) {
                const float2 r0 = *(const float2*)(res + idx0);
                const float2 r1 = *(const float2*)(res + idx1);
                o00 += r0.x; o01 += r0.y;
                o10 += r1.x; o11 += r1.y;
            }
            if constexpr (sizeof(OutT) == 2) {
                *(uint32_t*)(C + idx0) = pack_h2(o00, o01);
                *(uint32_t*)(C + idx1) = pack_h2(o10, o11);
            } else {
                *(float2*)(C + idx0) = make_float2(o00, o01);
                *(float2*)(C + idx1) = make_float2(o10, o11);
            }
        }
    }
}

// ---------------------------------------------------------------------------
// Full-f16 tensor-core attention, HPB heads per block.
// Block stages HPB heads' Q/K/V; 4 warps share HPB*QT q-tiles (multiple of 4).
// flat(n,s) = cd*(n/d0) + cm*(n%d0) + cs*s
// ---------------------------------------------------------------------------
template<int S, int HPB>
__global__ __launch_bounds__(128) void attn_mma_kernel(
    const __half* __restrict__ qkv, __half* __restrict__ att,
    const float* __restrict__ rsin, const float* __restrict__ rcos,
    int d0, int cd, int cm, int cs)
{
    constexpr int NT    = (S + 7) / 8;
    constexpr int QT    = (S + 15) / 16;
    constexpr int KT2   = NT / 2;
    constexpr int NT8   = NT * 8;
    constexpr int D8    = (8 - (NT8 % 32) + 32) % 32;
    constexpr int D24   = (24 - (NT8 % 32) + 32) % 32;
    constexpr int KSTR2 = NT8 + (D8 < D24 ? D8 : D24);  // stride %32 in {8,24}
    constexpr int QROWS = QT * 16;
    static_assert((HPB * QT) % 4 == 0, "tiles must divide among 4 warps");

    __shared__ uint32_t Qp[HPB][QROWS][20];
    __shared__ uint32_t Ktp[HPB][16][KSTR2];
    __shared__ uint32_t Vp[HPB][NT * 4][40];

    int n = blockIdx.x;
    int hg0 = blockIdx.y * HPB;
    int tid = threadIdx.x;
    int lane = tid & 31;
    int warp = tid >> 5;
    int r = lane >> 2;
    int c = lane & 3;

    int nb = cd * (n / d0) + cm * (n % d0);
    const float scale = 0.17677669529663687f;

    // ---- Stage Q (rotated + pre-scaled, f16 pairs; zero-padded rows) ----
    for (int idx = tid; idx < HPB * QROWS * 16; idx += 128) {
        int p = idx & 15;
        int j = (idx >> 4) % QROWS;
        int hh = (idx >> 4) / QROWS;
        uint32_t w = 0;
        if (j < S) {
            size_t rowb = (size_t)(nb + cs * j) * (3 * DD) + (hg0 + hh) * HD;
            float f0, f1;
            if (rsin) {
                if (p < 8) {
                    int d0i = 2 * p, d1i = 2 * p + 1;
                    f0 = __half2float(qkv[rowb + 2 * d0i]) * rcos[j * 16 + d0i]
                       - __half2float(qkv[rowb + 2 * d0i + 1]) * rsin[j * 16 + d0i];
                    f1 = __half2float(qkv[rowb + 2 * d1i]) * rcos[j * 16 + d1i]
                       - __half2float(qkv[rowb + 2 * d1i + 1]) * rsin[j * 16 + d1i];
                } else {
                    int i0 = 2 * p - 16, i1 = 2 * p - 15;
                    f0 = __half2float(qkv[rowb + 2 * i0]) * rsin[j * 16 + i0]
                       + __half2float(qkv[rowb + 2 * i0 + 1]) * rcos[j * 16 + i0];
                    f1 = __half2float(qkv[rowb + 2 * i1]) * rsin[j * 16 + i1]
                       + __half2float(qkv[rowb + 2 * i1 + 1]) * rcos[j * 16 + i1];
                }
            } else {
                f0 = __half2float(qkv[rowb + 2 * p]);
                f1 = __half2float(qkv[rowb + 2 * p + 1]);
            }
            w = pack_h2(f0 * scale, f1 * scale);
        }
        Qp[hh][j][p] = w;
    }
    // ---- Stage K^T: row-major over tokens (coalesced); write transposed ----
    for (int idx = tid; idx < HPB * NT8 * 16; idx += 128) {
        int p = idx & 15;
        int j = (idx >> 4) % NT8;
        int hh = (idx >> 4) / NT8;
        uint32_t w = 0;
        if (j < S) {
            size_t rowb = (size_t)(nb + cs * j) * (3 * DD) + DD + (hg0 + hh) * HD;
            float f0, f1;
            if (rsin) {
                if (p < 8) {
                    int d0i = 2 * p, d1i = 2 * p + 1;
                    f0 = __half2float(qkv[rowb + 2 * d0i]) * rcos[j * 16 + d0i]
                       - __half2float(qkv[rowb + 2 * d0i + 1]) * rsin[j * 16 + d0i];
                    f1 = __half2float(qkv[rowb + 2 * d1i]) * rcos[j * 16 + d1i]
                       - __half2float(qkv[rowb + 2 * d1i + 1]) * rsin[j * 16 + d1i];
                } else {
                    int i0 = 2 * p - 16, i1 = 2 * p - 15;
                    f0 = __half2float(qkv[rowb + 2 * i0]) * rsin[j * 16 + i0]
                       + __half2float(qkv[rowb + 2 * i0 + 1]) * rcos[j * 16 + i0];
                    f1 = __half2float(qkv[rowb + 2 * i1]) * rsin[j * 16 + i1]
                       + __half2float(qkv[rowb + 2 * i1 + 1]) * rcos[j * 16 + i1];
                }
                w = pack_h2(f0, f1);
            } else {
                __half h0 = qkv[rowb + 2 * p];
                __half h1 = qkv[rowb + 2 * p + 1];
                __half2 t = __halves2half2(h0, h1);
                w = *(uint32_t*)&t;
            }
        }
        Ktp[hh][p][j] = w;
    }
    // ---- Stage V as f16 (j, j+1) pairs; zero-padded ----
    for (int idx = tid; idx < HPB * NT * 4 * 32; idx += 128) {
        int d = idx & 31;
        int j2 = (idx >> 5) % (NT * 4);
        int hh = (idx >> 5) / (NT * 4);
        int j0 = 2 * j2, j1 = 2 * j2 + 1;
        size_t voff = 2 * DD + (hg0 + hh) * HD;
        __half v0 = (j0 < S) ? qkv[(size_t)(nb + cs * j0) * (3 * DD) + voff + d] : __half(0.f);
        __half v1 = (j1 < S) ? qkv[(size_t)(nb + cs * j1) * (3 * DD) + voff + d] : __half(0.f);
        __half2 t = __halves2half2(v0, v1);
        Vp[hh][j2][d] = *(uint32_t*)&t;
    }
    __syncthreads();

    for (int t = warp; t < HPB * QT; t += 4) {
        int hh = t / QT;
        int qt = t % QT;
        int q0 = qt * 16;
        int hcur = hg0 + hh;

        uint32_t aq[2][4];
        #pragma unroll
        for (int s = 0; s < 2; s++) {
            aq[s][0] = Qp[hh][q0 + r][8 * s + c];
            aq[s][1] = Qp[hh][q0 + 8 + r][8 * s + c];
            aq[s][2] = Qp[hh][q0 + r][8 * s + c + 4];
            aq[s][3] = Qp[hh][q0 + 8 + r][8 * s + c + 4];
        }

        float sacc[NT][4];
        #pragma unroll
        for (int nt = 0; nt < NT; nt++)
            #pragma unroll
            for (int e = 0; e < 4; e++) sacc[nt][e] = 0.f;

        #pragma unroll
        for (int nt = 0; nt < NT; nt++) {
            #pragma unroll
            for (int s = 0; s < 2; s++) {
                uint32_t bk[2];
                bk[0] = Ktp[hh][8 * s + c][nt * 8 + r];
                bk[1] = Ktp[hh][8 * s + c + 4][nt * 8 + r];
                mma_f16(sacc[nt], aq[s], bk);
            }
        }

        #pragma unroll
        for (int nt = 0; nt < NT; nt++) {
            int col = nt * 8 + 2 * c;
            if (col >= S)     { sacc[nt][0] = -1e30f; sacc[nt][2] = -1e30f; }
            if (col + 1 >= S) { sacc[nt][1] = -1e30f; sacc[nt][3] = -1e30f; }
        }

        float m0 = -1e30f, m1 = -1e30f;
        #pragma unroll
        for (int nt = 0; nt < NT; nt++) {
            m0 = fmaxf(m0, fmaxf(sacc[nt][0], sacc[nt][1]));
            m1 = fmaxf(m1, fmaxf(sacc[nt][2], sacc[nt][3]));
        }
        m0 = fmaxf(m0, __shfl_xor_sync(0xffffffffu, m0, 1));
        m0 = fmaxf(m0, __shfl_xor_sync(0xffffffffu, m0, 2));
        m1 = fmaxf(m1, __shfl_xor_sync(0xffffffffu, m1, 1));
        m1 = fmaxf(m1, __shfl_xor_sync(0xffffffffu, m1, 2));

        float s0 = 0.f, s1 = 0.f;
        #pragma unroll
        for (int nt = 0; nt < NT; nt++) {
            sacc[nt][0] = __expf(sacc[nt][0] - m0);
            sacc[nt][1] = __expf(sacc[nt][1] - m0);
            sacc[nt][2] = __expf(sacc[nt][2] - m1);
            sacc[nt][3] = __expf(sacc[nt][3] - m1);
            s0 += sacc[nt][0] + sacc[nt][1];
            s1 += sacc[nt][2] + sacc[nt][3];
        }
        s0 += __shfl_xor_sync(0xffffffffu, s0, 1);
        s0 += __shfl_xor_sync(0xffffffffu, s0, 2);
        s1 += __shfl_xor_sync(0xffffffffu, s1, 1);
        s1 += __shfl_xor_sync(0xffffffffu, s1, 2);
        float rinv0 = 1.f / s0;
        float rinv1 = 1.f / s1;

        uint32_t pa[KT2][4];
        #pragma unroll
        for (int kt = 0; kt < KT2; kt++) {
            int nt0 = 2 * kt, nt1 = 2 * kt + 1;
            pa[kt][0] = pack_h2(sacc[nt0][0], sacc[nt0][1]);
            pa[kt][1] = pack_h2(sacc[nt0][2], sacc[nt0][3]);
            pa[kt][2] = pack_h2(sacc[nt1][0], sacc[nt1][1]);
            pa[kt][3] = pack_h2(sacc[nt1][2], sacc[nt1][3]);
        }

        float oacc[4][4];
        #pragma unroll
        for (int dt = 0; dt < 4; dt++)
            #pragma unroll
            for (int e = 0; e < 4; e++) oacc[dt][e] = 0.f;

        #pragma unroll
        for (int kt = 0; kt < KT2; kt++) {
            #pragma unroll
            for (int dt = 0; dt < 4; dt++) {
                uint32_t bv[2];
                bv[0] = Vp[hh][8 * kt + c][dt * 8 + r];
                bv[1] = Vp[hh][8 * kt + c + 4][dt * 8 + r];
                mma_f16(oacc[dt], pa[kt], bv);
            }
        }

        int row0 = q0 + r;
        int row1 = q0 + 8 + r;
        #pragma unroll
        for (int dt = 0; dt < 4; dt++) {
            if (row0 < S) {
                uint32_t o = pack_h2(oacc[dt][0] * rinv0, oacc[dt][1] * rinv0);
                *(uint32_t*)&att[(size_t)(nb + cs * row0) * DD + hcur * HD + dt * 8 + 2 * c] = o;
            }
            if (row1 < S) {
                uint32_t o = pack_h2(oacc[dt][2] * rinv1, oacc[dt][3] * rinv1);
                *(uint32_t*)&att[(size_t)(nb + cs * row1) * DD + hcur * HD + dt * 8 + 2 * c] = o;
            }
        }
    }
}

// ---------------------------------------------------------------------------
// Host launcher
// ---------------------------------------------------------------------------
extern "C" void kernel_launch(void* const* d_in, const int* in_sizes, int n_in,
                              void* d_out, int out_size)
{
    const float* x         = (const float*)d_in[0];
    const float* lat_grid  = (const float*)d_in[1];
    const float* lon_grid  = (const float*)d_in[2];
    const float* lat_qkv_w = (const float*)d_in[3];
    const float* lat_qkv_b = (const float*)d_in[4];
    const float* lon_qkv_w = (const float*)d_in[5];
    const float* lon_qkv_b = (const float*)d_in[6];
    const float* lev_qkv_w = (const float*)d_in[7];
    const float* lev_qkv_b = (const float*)d_in[8];
    const float* proj_w    = (const float*)d_in[9];
    const float* proj_b    = (const float*)d_in[10];
    const float* g_lat     = (const float*)d_in[11];
    const float* b_lat     = (const float*)d_in[12];
    const float* g_lon     = (const float*)d_in[13];
    const float* b_lon     = (const float*)d_in[14];
    const float* g_lev     = (const float*)d_in[15];
    const float* b_lev     = (const float*)d_in[16];
    float* out = (float*)d_out;

    __half *lnh, *qkvh, *atth;
    float *state, *slat, *clat, *slon, *clon;
    uint32_t *wpq, *wpp;
    cudaGetSymbolAddress((void**)&lnh,   g_lnh);
    cudaGetSymbolAddress((void**)&qkvh,  g_qkvh);
    cudaGetSymbolAddress((void**)&atth,  g_atth);
    cudaGetSymbolAddress((void**)&state, g_state);
    cudaGetSymbolAddress((void**)&slat,  g_sin_lat);
    cudaGetSymbolAddress((void**)&clat,  g_cos_lat);
    cudaGetSymbolAddress((void**)&slon,  g_sin_lon);
    cudaGetSymbolAddress((void**)&clon,  g_cos_lon);
    cudaGetSymbolAddress((void**)&wpq,   g_wp_qkv);
    cudaGetSymbolAddress((void**)&wpp,   g_wp_proj);

    uint32_t* wp_lat = wpq;
    uint32_t* wp_lon = wpq + (size_t)(DD / 2) * 3 * DD;
    uint32_t* wp_lev = wpq + (size_t)2 * (DD / 2) * 3 * DD;

    pack_w_kernel<<<dim3(3 * DD / 256, DD / 2), 256>>>(lat_qkv_w, wp_lat, DD, 3 * DD);
    pack_w_kernel<<<dim3(3 * DD / 256, DD / 2), 256>>>(lon_qkv_w, wp_lon, DD, 3 * DD);
    pack_w_kernel<<<dim3(3 * DD / 256, DD / 2), 256>>>(lev_qkv_w, wp_lev, DD, 3 * DD);
    pack_w_kernel<<<dim3(DD / 256, DD / 2), 256>>>(proj_w, wpp, DD, DD);

    rotary_kernel<<<(HH * 16 + 127) / 128, 128>>>(lat_grid, HH, 0, slat, clat);
    rotary_kernel<<<(WW * 16 + 127) / 128, 128>>>(lon_grid, WW, 1, slon, clon);

    dim3 gq(3 * DD / 128, TT / 128);   // (12, 468)
    dim3 gp(DD / 128, TT / 128);       // (4, 468)

    // ---- lat block (seq = H, n over (l,w)) ----
    ln_kernel<<<TT / 8, 256>>>(x, g_lat, b_lat, lnh);
    gemm_f16_kernel<__half><<<gq, 128>>>(lnh, wp_lat, lat_qkv_b, nullptr, qkvh, TT, 3 * DD, DD);
    attn_mma_kernel<HH, 4><<<dim3(LL * WW, NHEAD / 4), 128>>>(qkvh, atth, slat, clat,
                                                              WW, HH * WW, 1, WW);
    gemm_f16_kernel<float><<<gp, 128>>>(atth, wpp, proj_b, x, state, TT, DD, DD);

    // ---- lon block (seq = W, n over (l,h)) ----
    ln_kernel<<<TT / 8, 256>>>(state, g_lon, b_lon, lnh);
    gemm_f16_kernel<__half><<<gq, 128>>>(lnh, wp_lon, lon_qkv_b, nullptr, qkvh, TT, 3 * DD, DD);
    attn_mma_kernel<WW, 2><<<dim3(LL * HH, NHEAD / 2), 128>>>(qkvh, atth, slon, clon,
                                                              1, WW, 0, 1);
    gemm_f16_kernel<float><<<gp, 128>>>(atth, wpp, proj_b, state, state, TT, DD, DD);

    // ---- lev block (seq = L, n over (h,w), no rotary) ----
    ln_kernel<<<TT / 8, 256>>>(state, g_lev, b_lev, lnh);
    gemm_f16_kernel<__half><<<gq, 128>>>(lnh, wp_lev, lev_qkv_b, nullptr, qkvh, TT, 3 * DD, DD);
    attn_mma_kernel<LL, 4><<<dim3(HH * WW, NHEAD / 4), 128>>>(qkvh, atth, nullptr, nullptr,
                                                              1, 1, 0, HH * WW);
    gemm_f16_kernel<float><<<gp, 128>>>(atth, wpp, proj_b, state, out, TT, DD, DD);
}

// round 13
// speedup vs baseline: 1.0548x; 1.0548x over previous
#include <cuda_runtime.h>
#include <cuda_bf16.h>
#include <cuda_fp16.h>
#include <math.h>
#include <stdint.h>

// Problem constants
#define LL 13
#define HH 48
#define WW 96
#define DD 512
#define TT (LL*HH*WW)        // 59904 tokens
#define NHEAD 16
#define HD 32

// Scratch (device globals; no cudaMalloc allowed)
__device__ __half g_lnh[(size_t)TT * DD];          // LN output (GEMM A), f16
__device__ __half g_qkvh[(size_t)TT * 3 * DD];     // QKV output, f16
__device__ __half g_atth[(size_t)TT * DD];         // attention output (proj A), f16
__device__ float  g_state[(size_t)TT * DD];        // residual stream, fp32
__device__ float  g_sin_lat[HH * 16];
__device__ float  g_cos_lat[HH * 16];
__device__ float  g_sin_lon[WW * 16];
__device__ float  g_cos_lon[WW * 16];
__device__ uint32_t g_wp_qkv[3][(DD / 2) * 3 * DD];  // packed f16 weights [K/2][N]
__device__ uint32_t g_wp_proj[(DD / 2) * DD];

// ---------------------------------------------------------------------------
// MMA + helpers
// ---------------------------------------------------------------------------
__device__ __forceinline__ void mma_f16(float* d, const uint32_t* a, const uint32_t* b)
{
    asm volatile(
        "mma.sync.aligned.m16n8k16.row.col.f32.f16.f16.f32 "
        "{%0,%1,%2,%3}, {%4,%5,%6,%7}, {%8,%9}, {%0,%1,%2,%3};"
        : "+f"(d[0]), "+f"(d[1]), "+f"(d[2]), "+f"(d[3])
        : "r"(a[0]), "r"(a[1]), "r"(a[2]), "r"(a[3]), "r"(b[0]), "r"(b[1]));
}

__device__ __forceinline__ uint32_t pack_h2(float lo, float hi)
{
    __half2 t = __floats2half2_rn(lo, hi);
    return *(uint32_t*)&t;
}

__device__ __forceinline__ void cp_async16(uint32_t dst, const void* src)
{
    asm volatile("cp.async.cg.shared.global [%0], [%1], 16;\n" :: "r"(dst), "l"(src));
}
__device__ __forceinline__ void cp_commit()
{
    asm volatile("cp.async.commit_group;\n" ::: "memory");
}
__device__ __forceinline__ void cp_wait0()
{
    asm volatile("cp.async.wait_group 0;\n" ::: "memory");
}

// ---------------------------------------------------------------------------
// Weight pack: W[K][N] fp32 -> out[k2][n] = half2(W[2k2][n], W[2k2+1][n])
// ---------------------------------------------------------------------------
__global__ void pack_w_kernel(const float* __restrict__ W, uint32_t* __restrict__ out,
                              int K, int N)
{
    int n  = blockIdx.x * 256 + threadIdx.x;
    int k2 = blockIdx.y;
    if (n < N)
        out[(size_t)k2 * N + n] =
            pack_h2(W[(size_t)(2 * k2) * N + n], W[(size_t)(2 * k2 + 1) * N + n]);
}

// ---------------------------------------------------------------------------
// Rotary sin/cos precompute. mode 0: lat axis (lon=0), mode 1: lon axis (lat=0)
// ---------------------------------------------------------------------------
__global__ void rotary_kernel(const float* __restrict__ grid, int S, int mode,
                              float* __restrict__ sout, float* __restrict__ cout)
{
    int idx = blockIdx.x * blockDim.x + threadIdx.x;
    if (idx >= S * 16) return;
    int s = idx >> 4;
    int f = idx & 15;
    const float PI = 3.14159265358979323846f;
    float lat, lon;
    if (mode == 0) { lat = grid[s]; lon = 0.f; }
    else           { lat = 0.f;     lon = grid[s]; }
    float two_pi = 2.f * PI;
    float r = fmodf(lon + PI, two_pi);
    if (r < 0.f) r += two_pi;
    float lonw = r - PI;
    float lo = -(PI * 0.5f) + 1e-6f;
    float hi =  (PI * 0.5f) - 1e-6f;
    float latc = fminf(fmaxf(lat, lo), hi);
    float invf = powf(10000.f, -(float)f / 16.f);
    float phase = (latc + lonw * cosf(latc)) * invf;
    sout[idx] = sinf(phase);
    cout[idx] = cosf(phase);
}

// ---------------------------------------------------------------------------
// LayerNorm, warp-per-token (no smem, no block barriers). 256 thr = 8 tokens.
// ---------------------------------------------------------------------------
__global__ void ln_kernel(const float* __restrict__ x, const float* __restrict__ g,
                          const float* __restrict__ b, __half* __restrict__ out)
{
    int warp = threadIdx.x >> 5, lane = threadIdx.x & 31;
    int t = blockIdx.x * 8 + warp;
    const float* row = x + (size_t)t * DD;

    float4 v[4];
    float s = 0.f, q = 0.f;
    #pragma unroll
    for (int k = 0; k < 4; k++) {
        v[k] = *(const float4*)(row + lane * 4 + 128 * k);
        s += v[k].x + v[k].y + v[k].z + v[k].w;
        q += v[k].x*v[k].x + v[k].y*v[k].y + v[k].z*v[k].z + v[k].w*v[k].w;
    }
    #pragma unroll
    for (int o = 16; o; o >>= 1) {
        s += __shfl_xor_sync(0xffffffffu, s, o);
        q += __shfl_xor_sync(0xffffffffu, q, o);
    }
    float mean = s * (1.f / 512.f);
    float var  = q * (1.f / 512.f) - mean * mean;
    float inv = rsqrtf(var + 1e-5f);

    #pragma unroll
    for (int k = 0; k < 4; k++) {
        float4 gv = *(const float4*)(g + lane * 4 + 128 * k);
        float4 bv = *(const float4*)(b + lane * 4 + 128 * k);
        uint2 o;
        o.x = pack_h2((v[k].x - mean) * inv * gv.x + bv.x,
                      (v[k].y - mean) * inv * gv.y + bv.y);
        o.y = pack_h2((v[k].z - mean) * inv * gv.z + bv.z,
                      (v[k].w - mean) * inv * gv.w + bv.w);
        *(uint2*)(out + (size_t)t * DD + lane * 4 + 128 * k) = o;
    }
}

// ---------------------------------------------------------------------------
// F16 tensor-core GEMM (round-8 proven structure): C = A@B + bias (+ res)
// ---------------------------------------------------------------------------
__device__ __forceinline__ void gemm_issue_chunk(
    const __half* __restrict__ A, const uint32_t* __restrict__ Bp,
    int N, int K, int m0, int n0, int tid,
    uint32_t as_base, uint32_t bs_base,
    int chunk, int buf)
{
    int k0 = chunk * 32;
    int arow = tid >> 2;
    int aq   = tid & 3;
    #pragma unroll
    for (int i = 0; i < 4; i++) {
        int row = arow + 32 * i;
        uint32_t dst = as_base + (uint32_t)(((buf * 128 + row) * 20 + aq * 4) * 4);
        cp_async16(dst, A + (size_t)(m0 + row) * K + k0 + aq * 8);
    }
    int bk = tid >> 5;
    int bt = tid & 31;
    #pragma unroll
    for (int i = 0; i < 4; i++) {
        int krow = bk + 4 * i;
        uint32_t dst = bs_base + (uint32_t)(((buf * 16 + krow) * 136 + bt * 4) * 4);
        cp_async16(dst, Bp + (size_t)(k0 / 2 + krow) * N + n0 + bt * 4);
    }
    cp_commit();
}

template<typename OutT>
__global__ __launch_bounds__(128) void gemm_f16_kernel(
    const __half* __restrict__ A, const uint32_t* __restrict__ Bp,
    const float* __restrict__ bias, const float* __restrict__ res,
    OutT* __restrict__ C, int M, int N, int K)
{
    __shared__ uint32_t Au[2][128][20];
    __shared__ uint32_t Bu[2][16][136];

    int tid  = threadIdx.x;
    int lane = tid & 31;
    int warp = tid >> 5;
    int wm   = warp >> 1;
    int wn   = warp & 1;
    int r    = lane >> 2;
    int c    = lane & 3;

    int m0 = blockIdx.y * 128;
    int n0 = blockIdx.x * 128;

    uint32_t as_base = (uint32_t)__cvta_generic_to_shared(&Au[0][0][0]);
    uint32_t bs_base = (uint32_t)__cvta_generic_to_shared(&Bu[0][0][0]);

    float acc[4][8][4];
    #pragma unroll
    for (int i = 0; i < 4; i++)
        #pragma unroll
        for (int j = 0; j < 8; j++)
            #pragma unroll
            for (int e = 0; e < 4; e++) acc[i][j][e] = 0.f;

    const int NCHUNK = K / 32;

    gemm_issue_chunk(A, Bp, N, K, m0, n0, tid, as_base, bs_base, 0, 0);

    for (int chunk = 0; chunk < NCHUNK; chunk++) {
        int buf = chunk & 1;
        cp_wait0();
        __syncthreads();

        if (chunk + 1 < NCHUNK)
            gemm_issue_chunk(A, Bp, N, K, m0, n0, tid,
                             as_base, bs_base, chunk + 1, buf ^ 1);

        #pragma unroll
        for (int ks = 0; ks < 2; ks++) {
            int kb = ks * 8;
            uint32_t afrag[4][4];
            #pragma unroll
            for (int i = 0; i < 4; i++) {
                int row = wm * 64 + i * 16 + r;
                afrag[i][0] = Au[buf][row][kb + c];
                afrag[i][1] = Au[buf][row + 8][kb + c];
                afrag[i][2] = Au[buf][row][kb + c + 4];
                afrag[i][3] = Au[buf][row + 8][kb + c + 4];
            }
            uint32_t bfrag[8][2];
            #pragma unroll
            for (int j = 0; j < 8; j++) {
                int col = wn * 64 + j * 8 + r;
                bfrag[j][0] = Bu[buf][kb + c][col];
                bfrag[j][1] = Bu[buf][kb + c + 4][col];
            }
            #pragma unroll
            for (int i = 0; i < 4; i++)
                #pragma unroll
                for (int j = 0; j < 8; j++)
                    mma_f16(acc[i][j], afrag[i], bfrag[j]);
        }
        __syncthreads();
    }

    #pragma unroll
    for (int i = 0; i < 4; i++) {
        int row0 = m0 + wm * 64 + i * 16 + r;
        #pragma unroll
        for (int j = 0; j < 8; j++) {
            int col = n0 + wn * 64 + j * 8 + 2 * c;
            float bv0 = bias[col];
            float bv1 = bias[col + 1];
            size_t idx0 = (size_t)row0 * N + col;
            size_t idx1 = (size_t)(row0 + 8) * N + col;
            float o00 = acc[i][j][0] + bv0, o01 = acc[i][j][1] + bv1;
            float o10 = acc[i][j][2] + bv0, o11 = acc[i][j][3] + bv1;
            if (res) {
                const float2 r0 = *(const float2*)(res + idx0);
                const float2 r1 = *(const float2*)(res + idx1);
                o00 += r0.x; o01 += r0.y;
                o10 += r1.x; o11 += r1.y;
            }
            if constexpr (sizeof(OutT) == 2) {
                *(uint32_t*)(C + idx0) = pack_h2(o00, o01);
                *(uint32_t*)(C + idx1) = pack_h2(o10, o11);
            } else {
                *(float2*)(C + idx0) = make_float2(o00, o01);
                *(float2*)(C + idx1) = make_float2(o10, o11);
            }
        }
    }
}

// ---------------------------------------------------------------------------
// Full-f16 tensor-core attention, HPB heads per block.
// HPB=1 for lat/lon (round-11 proven config); HPB=4 only for lev (S=13),
// where per-head blocks left 3/4 warps idle and smem stays small (~16 KB).
// flat(n,s) = cd*(n/d0) + cm*(n%d0) + cs*s
// ---------------------------------------------------------------------------
template<int S, int HPB>
__global__ __launch_bounds__(128) void attn_mma_kernel(
    const __half* __restrict__ qkv, __half* __restrict__ att,
    const float* __restrict__ rsin, const float* __restrict__ rcos,
    int d0, int cd, int cm, int cs)
{
    constexpr int NT    = (S + 7) / 8;
    constexpr int QT    = (S + 15) / 16;
    constexpr int KT2   = NT / 2;
    constexpr int NT8   = NT * 8;
    constexpr int D8    = (8 - (NT8 % 32) + 32) % 32;
    constexpr int D24   = (24 - (NT8 % 32) + 32) % 32;
    constexpr int KSTR2 = NT8 + (D8 < D24 ? D8 : D24);  // stride %32 in {8,24}
    constexpr int QROWS = QT * 16;

    __shared__ uint32_t Qp[HPB][QROWS][20];
    __shared__ uint32_t Ktp[HPB][16][KSTR2];
    __shared__ uint32_t Vp[HPB][NT * 4][40];

    int n = blockIdx.x;
    int hg0 = blockIdx.y * HPB;
    int tid = threadIdx.x;
    int lane = tid & 31;
    int warp = tid >> 5;
    int r = lane >> 2;
    int c = lane & 3;

    int nb = cd * (n / d0) + cm * (n % d0);
    const float scale = 0.17677669529663687f;

    // ---- Stage Q (rotated + pre-scaled, f16 pairs; zero-padded rows) ----
    for (int idx = tid; idx < HPB * QROWS * 16; idx += 128) {
        int p = idx & 15;
        int j = (idx >> 4) % QROWS;
        int hh = (idx >> 4) / QROWS;
        uint32_t w = 0;
        if (j < S) {
            size_t rowb = (size_t)(nb + cs * j) * (3 * DD) + (hg0 + hh) * HD;
            float f0, f1;
            if (rsin) {
                if (p < 8) {
                    int d0i = 2 * p, d1i = 2 * p + 1;
                    f0 = __half2float(qkv[rowb + 2 * d0i]) * rcos[j * 16 + d0i]
                       - __half2float(qkv[rowb + 2 * d0i + 1]) * rsin[j * 16 + d0i];
                    f1 = __half2float(qkv[rowb + 2 * d1i]) * rcos[j * 16 + d1i]
                       - __half2float(qkv[rowb + 2 * d1i + 1]) * rsin[j * 16 + d1i];
                } else {
                    int i0 = 2 * p - 16, i1 = 2 * p - 15;
                    f0 = __half2float(qkv[rowb + 2 * i0]) * rsin[j * 16 + i0]
                       + __half2float(qkv[rowb + 2 * i0 + 1]) * rcos[j * 16 + i0];
                    f1 = __half2float(qkv[rowb + 2 * i1]) * rsin[j * 16 + i1]
                       + __half2float(qkv[rowb + 2 * i1 + 1]) * rcos[j * 16 + i1];
                }
            } else {
                f0 = __half2float(qkv[rowb + 2 * p]);
                f1 = __half2float(qkv[rowb + 2 * p + 1]);
            }
            w = pack_h2(f0 * scale, f1 * scale);
        }
        Qp[hh][j][p] = w;
    }
    // ---- Stage K^T: row-major over tokens (coalesced); write transposed ----
    for (int idx = tid; idx < HPB * NT8 * 16; idx += 128) {
        int p = idx & 15;
        int j = (idx >> 4) % NT8;
        int hh = (idx >> 4) / NT8;
        uint32_t w = 0;
        if (j < S) {
            size_t rowb = (size_t)(nb + cs * j) * (3 * DD) + DD + (hg0 + hh) * HD;
            float f0, f1;
            if (rsin) {
                if (p < 8) {
                    int d0i = 2 * p, d1i = 2 * p + 1;
                    f0 = __half2float(qkv[rowb + 2 * d0i]) * rcos[j * 16 + d0i]
                       - __half2float(qkv[rowb + 2 * d0i + 1]) * rsin[j * 16 + d0i];
                    f1 = __half2float(qkv[rowb + 2 * d1i]) * rcos[j * 16 + d1i]
                       - __half2float(qkv[rowb + 2 * d1i + 1]) * rsin[j * 16 + d1i];
                } else {
                    int i0 = 2 * p - 16, i1 = 2 * p - 15;
                    f0 = __half2float(qkv[rowb + 2 * i0]) * rsin[j * 16 + i0]
                       + __half2float(qkv[rowb + 2 * i0 + 1]) * rcos[j * 16 + i0];
                    f1 = __half2float(qkv[rowb + 2 * i1]) * rsin[j * 16 + i1]
                       + __half2float(qkv[rowb + 2 * i1 + 1]) * rcos[j * 16 + i1];
                }
                w = pack_h2(f0, f1);
            } else {
                __half h0 = qkv[rowb + 2 * p];
                __half h1 = qkv[rowb + 2 * p + 1];
                __half2 t = __halves2half2(h0, h1);
                w = *(uint32_t*)&t;
            }
        }
        Ktp[hh][p][j] = w;
    }
    // ---- Stage V as f16 (j, j+1) pairs; zero-padded ----
    for (int idx = tid; idx < HPB * NT * 4 * 32; idx += 128) {
        int d = idx & 31;
        int j2 = (idx >> 5) % (NT * 4);
        int hh = (idx >> 5) / (NT * 4);
        int j0 = 2 * j2, j1 = 2 * j2 + 1;
        size_t voff = 2 * DD + (hg0 + hh) * HD;
        __half v0 = (j0 < S) ? qkv[(size_t)(nb + cs * j0) * (3 * DD) + voff + d] : __half(0.f);
        __half v1 = (j1 < S) ? qkv[(size_t)(nb + cs * j1) * (3 * DD) + voff + d] : __half(0.f);
        __half2 t = __halves2half2(v0, v1);
        Vp[hh][j2][d] = *(uint32_t*)&t;
    }
    __syncthreads();

    for (int t = warp; t < HPB * QT; t += 4) {
        int hh = t / QT;
        int qt = t % QT;
        int q0 = qt * 16;
        int hcur = hg0 + hh;

        uint32_t aq[2][4];
        #pragma unroll
        for (int s = 0; s < 2; s++) {
            aq[s][0] = Qp[hh][q0 + r][8 * s + c];
            aq[s][1] = Qp[hh][q0 + 8 + r][8 * s + c];
            aq[s][2] = Qp[hh][q0 + r][8 * s + c + 4];
            aq[s][3] = Qp[hh][q0 + 8 + r][8 * s + c + 4];
        }

        float sacc[NT][4];
        #pragma unroll
        for (int nt = 0; nt < NT; nt++)
            #pragma unroll
            for (int e = 0; e < 4; e++) sacc[nt][e] = 0.f;

        #pragma unroll
        for (int nt = 0; nt < NT; nt++) {
            #pragma unroll
            for (int s = 0; s < 2; s++) {
                uint32_t bk[2];
                bk[0] = Ktp[hh][8 * s + c][nt * 8 + r];
                bk[1] = Ktp[hh][8 * s + c + 4][nt * 8 + r];
                mma_f16(sacc[nt], aq[s], bk);
            }
        }

        #pragma unroll
        for (int nt = 0; nt < NT; nt++) {
            int col = nt * 8 + 2 * c;
            if (col >= S)     { sacc[nt][0] = -1e30f; sacc[nt][2] = -1e30f; }
            if (col + 1 >= S) { sacc[nt][1] = -1e30f; sacc[nt][3] = -1e30f; }
        }

        float m0 = -1e30f, m1 = -1e30f;
        #pragma unroll
        for (int nt = 0; nt < NT; nt++) {
            m0 = fmaxf(m0, fmaxf(sacc[nt][0], sacc[nt][1]));
            m1 = fmaxf(m1, fmaxf(sacc[nt][2], sacc[nt][3]));
        }
        m0 = fmaxf(m0, __shfl_xor_sync(0xffffffffu, m0, 1));
        m0 = fmaxf(m0, __shfl_xor_sync(0xffffffffu, m0, 2));
        m1 = fmaxf(m1, __shfl_xor_sync(0xffffffffu, m1, 1));
        m1 = fmaxf(m1, __shfl_xor_sync(0xffffffffu, m1, 2));

        float s0 = 0.f, s1 = 0.f;
        #pragma unroll
        for (int nt = 0; nt < NT; nt++) {
            sacc[nt][0] = __expf(sacc[nt][0] - m0);
            sacc[nt][1] = __expf(sacc[nt][1] - m0);
            sacc[nt][2] = __expf(sacc[nt][2] - m1);
            sacc[nt][3] = __expf(sacc[nt][3] - m1);
            s0 += sacc[nt][0] + sacc[nt][1];
            s1 += sacc[nt][2] + sacc[nt][3];
        }
        s0 += __shfl_xor_sync(0xffffffffu, s0, 1);
        s0 += __shfl_xor_sync(0xffffffffu, s0, 2);
        s1 += __shfl_xor_sync(0xffffffffu, s1, 1);
        s1 += __shfl_xor_sync(0xffffffffu, s1, 2);
        float rinv0 = 1.f / s0;
        float rinv1 = 1.f / s1;

        uint32_t pa[KT2][4];
        #pragma unroll
        for (int kt = 0; kt < KT2; kt++) {
            int nt0 = 2 * kt, nt1 = 2 * kt + 1;
            pa[kt][0] = pack_h2(sacc[nt0][0], sacc[nt0][1]);
            pa[kt][1] = pack_h2(sacc[nt0][2], sacc[nt0][3]);
            pa[kt][2] = pack_h2(sacc[nt1][0], sacc[nt1][1]);
            pa[kt][3] = pack_h2(sacc[nt1][2], sacc[nt1][3]);
        }

        float oacc[4][4];
        #pragma unroll
        for (int dt = 0; dt < 4; dt++)
            #pragma unroll
            for (int e = 0; e < 4; e++) oacc[dt][e] = 0.f;

        #pragma unroll
        for (int kt = 0; kt < KT2; kt++) {
            #pragma unroll
            for (int dt = 0; dt < 4; dt++) {
                uint32_t bv[2];
                bv[0] = Vp[hh][8 * kt + c][dt * 8 + r];
                bv[1] = Vp[hh][8 * kt + c + 4][dt * 8 + r];
                mma_f16(oacc[dt], pa[kt], bv);
            }
        }

        int row0 = q0 + r;
        int row1 = q0 + 8 + r;
        #pragma unroll
        for (int dt = 0; dt < 4; dt++) {
            if (row0 < S) {
                uint32_t o = pack_h2(oacc[dt][0] * rinv0, oacc[dt][1] * rinv0);
                *(uint32_t*)&att[(size_t)(nb + cs * row0) * DD + hcur * HD + dt * 8 + 2 * c] = o;
            }
            if (row1 < S) {
                uint32_t o = pack_h2(oacc[dt][2] * rinv1, oacc[dt][3] * rinv1);
                *(uint32_t*)&att[(size_t)(nb + cs * row1) * DD + hcur * HD + dt * 8 + 2 * c] = o;
            }
        }
    }
}

// ---------------------------------------------------------------------------
// Host launcher
// ---------------------------------------------------------------------------
extern "C" void kernel_launch(void* const* d_in, const int* in_sizes, int n_in,
                              void* d_out, int out_size)
{
    const float* x         = (const float*)d_in[0];
    const float* lat_grid  = (const float*)d_in[1];
    const float* lon_grid  = (const float*)d_in[2];
    const float* lat_qkv_w = (const float*)d_in[3];
    const float* lat_qkv_b = (const float*)d_in[4];
    const float* lon_qkv_w = (const float*)d_in[5];
    const float* lon_qkv_b = (const float*)d_in[6];
    const float* lev_qkv_w = (const float*)d_in[7];
    const float* lev_qkv_b = (const float*)d_in[8];
    const float* proj_w    = (const float*)d_in[9];
    const float* proj_b    = (const float*)d_in[10];
    const float* g_lat     = (const float*)d_in[11];
    const float* b_lat     = (const float*)d_in[12];
    const float* g_lon     = (const float*)d_in[13];
    const float* b_lon     = (const float*)d_in[14];
    const float* g_lev     = (const float*)d_in[15];
    const float* b_lev     = (const float*)d_in[16];
    float* out = (float*)d_out;

    __half *lnh, *qkvh, *atth;
    float *state, *slat, *clat, *slon, *clon;
    uint32_t *wpq, *wpp;
    cudaGetSymbolAddress((void**)&lnh,   g_lnh);
    cudaGetSymbolAddress((void**)&qkvh,  g_qkvh);
    cudaGetSymbolAddress((void**)&atth,  g_atth);
    cudaGetSymbolAddress((void**)&state, g_state);
    cudaGetSymbolAddress((void**)&slat,  g_sin_lat);
    cudaGetSymbolAddress((void**)&clat,  g_cos_lat);
    cudaGetSymbolAddress((void**)&slon,  g_sin_lon);
    cudaGetSymbolAddress((void**)&clon,  g_cos_lon);
    cudaGetSymbolAddress((void**)&wpq,   g_wp_qkv);
    cudaGetSymbolAddress((void**)&wpp,   g_wp_proj);

    uint32_t* wp_lat = wpq;
    uint32_t* wp_lon = wpq + (size_t)(DD / 2) * 3 * DD;
    uint32_t* wp_lev = wpq + (size_t)2 * (DD / 2) * 3 * DD;

    pack_w_kernel<<<dim3(3 * DD / 256, DD / 2), 256>>>(lat_qkv_w, wp_lat, DD, 3 * DD);
    pack_w_kernel<<<dim3(3 * DD / 256, DD / 2), 256>>>(lon_qkv_w, wp_lon, DD, 3 * DD);
    pack_w_kernel<<<dim3(3 * DD / 256, DD / 2), 256>>>(lev_qkv_w, wp_lev, DD, 3 * DD);
    pack_w_kernel<<<dim3(DD / 256, DD / 2), 256>>>(proj_w, wpp, DD, DD);

    rotary_kernel<<<(HH * 16 + 127) / 128, 128>>>(lat_grid, HH, 0, slat, clat);
    rotary_kernel<<<(WW * 16 + 127) / 128, 128>>>(lon_grid, WW, 1, slon, clon);

    dim3 gq(3 * DD / 128, TT / 128);   // (12, 468)
    dim3 gp(DD / 128, TT / 128);       // (4, 468)

    // ---- lat block (seq = H, n over (l,w)) ----
    ln_kernel<<<TT / 8, 256>>>(x, g_lat, b_lat, lnh);
    gemm_f16_kernel<__half><<<gq, 128>>>(lnh, wp_lat, lat_qkv_b, nullptr, qkvh, TT, 3 * DD, DD);
    attn_mma_kernel<HH, 1><<<dim3(LL * WW, NHEAD), 128>>>(qkvh, atth, slat, clat,
                                                          WW, HH * WW, 1, WW);
    gemm_f16_kernel<float><<<gp, 128>>>(atth, wpp, proj_b, x, state, TT, DD, DD);

    // ---- lon block (seq = W, n over (l,h)) ----
    ln_kernel<<<TT / 8, 256>>>(state, g_lon, b_lon, lnh);
    gemm_f16_kernel<__half><<<gq, 128>>>(lnh, wp_lon, lon_qkv_b, nullptr, qkvh, TT, 3 * DD, DD);
    attn_mma_kernel<WW, 1><<<dim3(LL * HH, NHEAD), 128>>>(qkvh, atth, slon, clon,
                                                          1, WW, 0, 1);
    gemm_f16_kernel<float><<<gp, 128>>>(atth, wpp, proj_b, state, state, TT, DD, DD);

    // ---- lev block (seq = L, n over (h,w), no rotary): HPB=4 fills warps ----
    ln_kernel<<<TT / 8, 256>>>(state, g_lev, b_lev, lnh);
    gemm_f16_kernel<__half><<<gq, 128>>>(lnh, wp_lev, lev_qkv_b, nullptr, qkvh, TT, 3 * DD, DD);
    attn_mma_kernel<LL, 4><<<dim3(HH * WW, NHEAD / 4), 128>>>(qkvh, atth, nullptr, nullptr,
                                                              1, 1, 0, HH * WW);
    gemm_f16_kernel<float><<<gp, 128>>>(atth, wpp, proj_b, state, out, TT, DD, DD);
}

// round 15
// speedup vs baseline: 1.0825x; 1.0262x over previous
#include <cuda_runtime.h>
#include <cuda_bf16.h>
#include <cuda_fp16.h>
#include <math.h>
#include <stdint.h>

// Problem constants
#define LL 13
#define HH 48
#define WW 96
#define DD 512
#define TT (LL*HH*WW)        // 59904 tokens
#define NHEAD 16
#define HD 32

// Scratch (device globals; no cudaMalloc allowed)
__device__ __half g_lnh[(size_t)TT * DD];          // LN output (GEMM A), f16
__device__ __half g_qkvh[(size_t)TT * 3 * DD];     // QKV output, f16
__device__ __half g_atth[(size_t)TT * DD];         // attention output (proj A), f16
__device__ __half g_stateh[(size_t)TT * DD];       // residual stream, f16
__device__ float  g_sin_lat[HH * 16];
__device__ float  g_cos_lat[HH * 16];
__device__ float  g_sin_lon[WW * 16];
__device__ float  g_cos_lon[WW * 16];
__device__ uint32_t g_wp_qkv[3][(DD / 2) * 3 * DD];  // packed f16 weights [K/2][N]
__device__ uint32_t g_wp_proj[(DD / 2) * DD];

// ---------------------------------------------------------------------------
// MMA + helpers
// ---------------------------------------------------------------------------
__device__ __forceinline__ void mma_f16(float* d, const uint32_t* a, const uint32_t* b)
{
    asm volatile(
        "mma.sync.aligned.m16n8k16.row.col.f32.f16.f16.f32 "
        "{%0,%1,%2,%3}, {%4,%5,%6,%7}, {%8,%9}, {%0,%1,%2,%3};"
        : "+f"(d[0]), "+f"(d[1]), "+f"(d[2]), "+f"(d[3])
        : "r"(a[0]), "r"(a[1]), "r"(a[2]), "r"(a[3]), "r"(b[0]), "r"(b[1]));
}

__device__ __forceinline__ uint32_t pack_h2(float lo, float hi)
{
    __half2 t = __floats2half2_rn(lo, hi);
    return *(uint32_t*)&t;
}

__device__ __forceinline__ float2 unpack_h2(uint32_t w)
{
    __half2 t = *(__half2*)&w;
    return __half22float2(t);
}

__device__ __forceinline__ void cp_async16(uint32_t dst, const void* src)
{
    asm volatile("cp.async.cg.shared.global [%0], [%1], 16;\n" :: "r"(dst), "l"(src));
}
__device__ __forceinline__ void cp_commit()
{
    asm volatile("cp.async.commit_group;\n" ::: "memory");
}
__device__ __forceinline__ void cp_wait0()
{
    asm volatile("cp.async.wait_group 0;\n" ::: "memory");
}

// ---------------------------------------------------------------------------
// Weight pack: W[K][N] fp32 -> out[k2][n] = half2(W[2k2][n], W[2k2+1][n])
// ---------------------------------------------------------------------------
__global__ void pack_w_kernel(const float* __restrict__ W, uint32_t* __restrict__ out,
                              int K, int N)
{
    int n  = blockIdx.x * 256 + threadIdx.x;
    int k2 = blockIdx.y;
    if (n < N)
        out[(size_t)k2 * N + n] =
            pack_h2(W[(size_t)(2 * k2) * N + n], W[(size_t)(2 * k2 + 1) * N + n]);
}

// ---------------------------------------------------------------------------
// Rotary sin/cos precompute. mode 0: lat axis (lon=0), mode 1: lon axis (lat=0)
// ---------------------------------------------------------------------------
__global__ void rotary_kernel(const float* __restrict__ grid, int S, int mode,
                              float* __restrict__ sout, float* __restrict__ cout)
{
    int idx = blockIdx.x * blockDim.x + threadIdx.x;
    if (idx >= S * 16) return;
    int s = idx >> 4;
    int f = idx & 15;
    const float PI = 3.14159265358979323846f;
    float lat, lon;
    if (mode == 0) { lat = grid[s]; lon = 0.f; }
    else           { lat = 0.f;     lon = grid[s]; }
    float two_pi = 2.f * PI;
    float r = fmodf(lon + PI, two_pi);
    if (r < 0.f) r += two_pi;
    float lonw = r - PI;
    float lo = -(PI * 0.5f) + 1e-6f;
    float hi =  (PI * 0.5f) - 1e-6f;
    float latc = fminf(fmaxf(lat, lo), hi);
    float invf = powf(10000.f, -(float)f / 16.f);
    float phase = (latc + lonw * cosf(latc)) * invf;
    sout[idx] = sinf(phase);
    cout[idx] = cosf(phase);
}

// ---------------------------------------------------------------------------
// LayerNorm, warp-per-token (no smem/barriers). 256 thr = 8 tokens.
// InT: float or __half.
// ---------------------------------------------------------------------------
template<typename InT>
__global__ void ln_kernel(const InT* __restrict__ x, const float* __restrict__ g,
                          const float* __restrict__ b, __half* __restrict__ out)
{
    int warp = threadIdx.x >> 5, lane = threadIdx.x & 31;
    int t = blockIdx.x * 8 + warp;
    const InT* row = x + (size_t)t * DD;

    float4 v[4];
    float s = 0.f, q = 0.f;
    #pragma unroll
    for (int k = 0; k < 4; k++) {
        if constexpr (sizeof(InT) == 2) {
            uint2 w = *(const uint2*)(row + lane * 4 + 128 * k);
            float2 lo = unpack_h2(w.x);
            float2 hi = unpack_h2(w.y);
            v[k] = make_float4(lo.x, lo.y, hi.x, hi.y);
        } else {
            v[k] = *(const float4*)(row + lane * 4 + 128 * k);
        }
        s += v[k].x + v[k].y + v[k].z + v[k].w;
        q += v[k].x*v[k].x + v[k].y*v[k].y + v[k].z*v[k].z + v[k].w*v[k].w;
    }
    #pragma unroll
    for (int o = 16; o; o >>= 1) {
        s += __shfl_xor_sync(0xffffffffu, s, o);
        q += __shfl_xor_sync(0xffffffffu, q, o);
    }
    float mean = s * (1.f / 512.f);
    float var  = q * (1.f / 512.f) - mean * mean;
    float inv = rsqrtf(var + 1e-5f);

    #pragma unroll
    for (int k = 0; k < 4; k++) {
        float4 gv = *(const float4*)(g + lane * 4 + 128 * k);
        float4 bv = *(const float4*)(b + lane * 4 + 128 * k);
        uint2 o;
        o.x = pack_h2((v[k].x - mean) * inv * gv.x + bv.x,
                      (v[k].y - mean) * inv * gv.y + bv.y);
        o.y = pack_h2((v[k].z - mean) * inv * gv.z + bv.z,
                      (v[k].w - mean) * inv * gv.w + bv.w);
        *(uint2*)(out + (size_t)t * DD + lane * 4 + 128 * k) = o;
    }
}

// ---------------------------------------------------------------------------
// F16 tensor-core GEMM: C = A@B + bias (+ res). OutT/ResT: float or __half.
// Block 128x128, 4 warps @64x64, BK=32, 2-stage cp.async, ONE sync per chunk.
// ---------------------------------------------------------------------------
__device__ __forceinline__ void gemm_issue_chunk(
    const __half* __restrict__ A, const uint32_t* __restrict__ Bp,
    int N, int K, int m0, int n0, int tid,
    uint32_t as_base, uint32_t bs_base,
    int chunk, int buf)
{
    int k0 = chunk * 32;
    int arow = tid >> 2;
    int aq   = tid & 3;
    #pragma unroll
    for (int i = 0; i < 4; i++) {
        int row = arow + 32 * i;
        uint32_t dst = as_base + (uint32_t)(((buf * 128 + row) * 20 + aq * 4) * 4);
        cp_async16(dst, A + (size_t)(m0 + row) * K + k0 + aq * 8);
    }
    int bk = tid >> 5;
    int bt = tid & 31;
    #pragma unroll
    for (int i = 0; i < 4; i++) {
        int krow = bk + 4 * i;
        uint32_t dst = bs_base + (uint32_t)(((buf * 16 + krow) * 136 + bt * 4) * 4);
        cp_async16(dst, Bp + (size_t)(k0 / 2 + krow) * N + n0 + bt * 4);
    }
    cp_commit();
}

template<typename OutT, typename ResT>
__global__ __launch_bounds__(128) void gemm_f16_kernel(
    const __half* __restrict__ A, const uint32_t* __restrict__ Bp,
    const float* __restrict__ bias, const ResT* __restrict__ res,
    OutT* __restrict__ C, int M, int N, int K)
{
    __shared__ uint32_t Au[2][128][20];
    __shared__ uint32_t Bu[2][16][136];

    int tid  = threadIdx.x;
    int lane = tid & 31;
    int warp = tid >> 5;
    int wm   = warp >> 1;
    int wn   = warp & 1;
    int r    = lane >> 2;
    int c    = lane & 3;

    int m0 = blockIdx.y * 128;
    int n0 = blockIdx.x * 128;

    uint32_t as_base = (uint32_t)__cvta_generic_to_shared(&Au[0][0][0]);
    uint32_t bs_base = (uint32_t)__cvta_generic_to_shared(&Bu[0][0][0]);

    float acc[4][8][4];
    #pragma unroll
    for (int i = 0; i < 4; i++)
        #pragma unroll
        for (int j = 0; j < 8; j++)
            #pragma unroll
            for (int e = 0; e < 4; e++) acc[i][j][e] = 0.f;

    const int NCHUNK = K / 32;

    gemm_issue_chunk(A, Bp, N, K, m0, n0, tid, as_base, bs_base, 0, 0);

    for (int chunk = 0; chunk < NCHUNK; chunk++) {
        int buf = chunk & 1;
        cp_wait0();
        __syncthreads();   // data ready + all warps done reading buf (prev iter)

        if (chunk + 1 < NCHUNK)
            gemm_issue_chunk(A, Bp, N, K, m0, n0, tid,
                             as_base, bs_base, chunk + 1, buf ^ 1);

        #pragma unroll
        for (int ks = 0; ks < 2; ks++) {
            int kb = ks * 8;
            uint32_t afrag[4][4];
            #pragma unroll
            for (int i = 0; i < 4; i++) {
                int row = wm * 64 + i * 16 + r;
                afrag[i][0] = Au[buf][row][kb + c];
                afrag[i][1] = Au[buf][row + 8][kb + c];
                afrag[i][2] = Au[buf][row][kb + c + 4];
                afrag[i][3] = Au[buf][row + 8][kb + c + 4];
            }
            uint32_t bfrag[8][2];
            #pragma unroll
            for (int j = 0; j < 8; j++) {
                int col = wn * 64 + j * 8 + r;
                bfrag[j][0] = Bu[buf][kb + c][col];
                bfrag[j][1] = Bu[buf][kb + c + 4][col];
            }
            #pragma unroll
            for (int i = 0; i < 4; i++)
                #pragma unroll
                for (int j = 0; j < 8; j++)
                    mma_f16(acc[i][j], afrag[i], bfrag[j]);
        }
        // NOTE: no trailing sync — next iteration's post-wait sync protects buf
    }

    #pragma unroll
    for (int i = 0; i < 4; i++) {
        int row0 = m0 + wm * 64 + i * 16 + r;
        #pragma unroll
        for (int j = 0; j < 8; j++) {
            int col = n0 + wn * 64 + j * 8 + 2 * c;
            float bv0 = bias[col];
            float bv1 = bias[col + 1];
            size_t idx0 = (size_t)row0 * N + col;
            size_t idx1 = (size_t)(row0 + 8) * N + col;
            float o00 = acc[i][j][0] + bv0, o01 = acc[i][j][1] + bv1;
            float o10 = acc[i][j][2] + bv0, o11 = acc[i][j][3] + bv1;
            if (res) {
                if constexpr (sizeof(ResT) == 2) {
                    float2 r0 = unpack_h2(*(const uint32_t*)(res + idx0));
                    float2 r1 = unpack_h2(*(const uint32_t*)(res + idx1));
                    o00 += r0.x; o01 += r0.y;
                    o10 += r1.x; o11 += r1.y;
                } else {
                    const float2 r0 = *(const float2*)(res + idx0);
                    const float2 r1 = *(const float2*)(res + idx1);
                    o00 += r0.x; o01 += r0.y;
                    o10 += r1.x; o11 += r1.y;
                }
            }
            if constexpr (sizeof(OutT) == 2) {
                *(uint32_t*)(C + idx0) = pack_h2(o00, o01);
                *(uint32_t*)(C + idx1) = pack_h2(o10, o11);
            } else {
                *(float2*)(C + idx0) = make_float2(o00, o01);
                *(float2*)(C + idx1) = make_float2(o10, o11);
            }
        }
    }
}

// ---------------------------------------------------------------------------
// Full-f16 tensor-core attention, HPB heads per block (HPB=1 lat/lon, 4 lev).
// flat(n,s) = cd*(n/d0) + cm*(n%d0) + cs*s
// ---------------------------------------------------------------------------
template<int S, int HPB>
__global__ __launch_bounds__(128) void attn_mma_kernel(
    const __half* __restrict__ qkv, __half* __restrict__ att,
    const float* __restrict__ rsin, const float* __restrict__ rcos,
    int d0, int cd, int cm, int cs)
{
    constexpr int NT    = (S + 7) / 8;
    constexpr int QT    = (S + 15) / 16;
    constexpr int KT2   = NT / 2;
    constexpr int NT8   = NT * 8;
    constexpr int D8    = (8 - (NT8 % 32) + 32) % 32;
    constexpr int D24   = (24 - (NT8 % 32) + 32) % 32;
    constexpr int KSTR2 = NT8 + (D8 < D24 ? D8 : D24);
    constexpr int QROWS = QT * 16;

    __shared__ uint32_t Qp[HPB][QROWS][20];
    __shared__ uint32_t Ktp[HPB][16][KSTR2];
    __shared__ uint32_t Vp[HPB][NT * 4][40];

    int n = blockIdx.x;
    int hg0 = blockIdx.y * HPB;
    int tid = threadIdx.x;
    int lane = tid & 31;
    int warp = tid >> 5;
    int r = lane >> 2;
    int c = lane & 3;

    int nb = cd * (n / d0) + cm * (n % d0);
    const float scale = 0.17677669529663687f;

    for (int idx = tid; idx < HPB * QROWS * 16; idx += 128) {
        int p = idx & 15;
        int j = (idx >> 4) % QROWS;
        int hh = (idx >> 4) / QROWS;
        uint32_t w = 0;
        if (j < S) {
            size_t rowb = (size_t)(nb + cs * j) * (3 * DD) + (hg0 + hh) * HD;
            float f0, f1;
            if (rsin) {
                if (p < 8) {
                    int d0i = 2 * p, d1i = 2 * p + 1;
                    f0 = __half2float(qkv[rowb + 2 * d0i]) * rcos[j * 16 + d0i]
                       - __half2float(qkv[rowb + 2 * d0i + 1]) * rsin[j * 16 + d0i];
                    f1 = __half2float(qkv[rowb + 2 * d1i]) * rcos[j * 16 + d1i]
                       - __half2float(qkv[rowb + 2 * d1i + 1]) * rsin[j * 16 + d1i];
                } else {
                    int i0 = 2 * p - 16, i1 = 2 * p - 15;
                    f0 = __half2float(qkv[rowb + 2 * i0]) * rsin[j * 16 + i0]
                       + __half2float(qkv[rowb + 2 * i0 + 1]) * rcos[j * 16 + i0];
                    f1 = __half2float(qkv[rowb + 2 * i1]) * rsin[j * 16 + i1]
                       + __half2float(qkv[rowb + 2 * i1 + 1]) * rcos[j * 16 + i1];
                }
            } else {
                f0 = __half2float(qkv[rowb + 2 * p]);
                f1 = __half2float(qkv[rowb + 2 * p + 1]);
            }
            w = pack_h2(f0 * scale, f1 * scale);
        }
        Qp[hh][j][p] = w;
    }
    for (int idx = tid; idx < HPB * NT8 * 16; idx += 128) {
        int p = idx & 15;
        int j = (idx >> 4) % NT8;
        int hh = (idx >> 4) / NT8;
        uint32_t w = 0;
        if (j < S) {
            size_t rowb = (size_t)(nb + cs * j) * (3 * DD) + DD + (hg0 + hh) * HD;
            float f0, f1;
            if (rsin) {
                if (p < 8) {
                    int d0i = 2 * p, d1i = 2 * p + 1;
                    f0 = __half2float(qkv[rowb + 2 * d0i]) * rcos[j * 16 + d0i]
                       - __half2float(qkv[rowb + 2 * d0i + 1]) * rsin[j * 16 + d0i];
                    f1 = __half2float(qkv[rowb + 2 * d1i]) * rcos[j * 16 + d1i]
                       - __half2float(qkv[rowb + 2 * d1i + 1]) * rsin[j * 16 + d1i];
                } else {
                    int i0 = 2 * p - 16, i1 = 2 * p - 15;
                    f0 = __half2float(qkv[rowb + 2 * i0]) * rsin[j * 16 + i0]
                       + __half2float(qkv[rowb + 2 * i0 + 1]) * rcos[j * 16 + i0];
                    f1 = __half2float(qkv[rowb + 2 * i1]) * rsin[j * 16 + i1]
                       + __half2float(qkv[rowb + 2 * i1 + 1]) * rcos[j * 16 + i1];
                }
                w = pack_h2(f0, f1);
            } else {
                __half h0 = qkv[rowb + 2 * p];
                __half h1 = qkv[rowb + 2 * p + 1];
                __half2 t = __halves2half2(h0, h1);
                w = *(uint32_t*)&t;
            }
        }
        Ktp[hh][p][j] = w;
    }
    for (int idx = tid; idx < HPB * NT * 4 * 32; idx += 128) {
        int d = idx & 31;
        int j2 = (idx >> 5) % (NT * 4);
        int hh = (idx >> 5) / (NT * 4);
        int j0 = 2 * j2, j1 = 2 * j2 + 1;
        size_t voff = 2 * DD + (hg0 + hh) * HD;
        __half v0 = (j0 < S) ? qkv[(size_t)(nb + cs * j0) * (3 * DD) + voff + d] : __half(0.f);
        __half v1 = (j1 < S) ? qkv[(size_t)(nb + cs * j1) * (3 * DD) + voff + d] : __half(0.f);
        __half2 t = __halves2half2(v0, v1);
        Vp[hh][j2][d] = *(uint32_t*)&t;
    }
    __syncthreads();

    for (int t = warp; t < HPB * QT; t += 4) {
        int hh = t / QT;
        int qt = t % QT;
        int q0 = qt * 16;
        int hcur = hg0 + hh;

        uint32_t aq[2][4];
        #pragma unroll
        for (int s = 0; s < 2; s++) {
            aq[s][0] = Qp[hh][q0 + r][8 * s + c];
            aq[s][1] = Qp[hh][q0 + 8 + r][8 * s + c];
            aq[s][2] = Qp[hh][q0 + r][8 * s + c + 4];
            aq[s][3] = Qp[hh][q0 + 8 + r][8 * s + c + 4];
        }

        float sacc[NT][4];
        #pragma unroll
        for (int nt = 0; nt < NT; nt++)
            #pragma unroll
            for (int e = 0; e < 4; e++) sacc[nt][e] = 0.f;

        #pragma unroll
        for (int nt = 0; nt < NT; nt++) {
            #pragma unroll
            for (int s = 0; s < 2; s++) {
                uint32_t bk[2];
                bk[0] = Ktp[hh][8 * s + c][nt * 8 + r];
                bk[1] = Ktp[hh][8 * s + c + 4][nt * 8 + r];
                mma_f16(sacc[nt], aq[s], bk);
            }
        }

        #pragma unroll
        for (int nt = 0; nt < NT; nt++) {
            int col = nt * 8 + 2 * c;
            if (col >= S)     { sacc[nt][0] = -1e30f; sacc[nt][2] = -1e30f; }
            if (col + 1 >= S) { sacc[nt][1] = -1e30f; sacc[nt][3] = -1e30f; }
        }

        float m0 = -1e30f, m1 = -1e30f;
        #pragma unroll
        for (int nt = 0; nt < NT; nt++) {
            m0 = fmaxf(m0, fmaxf(sacc[nt][0], sacc[nt][1]));
            m1 = fmaxf(m1, fmaxf(sacc[nt][2], sacc[nt][3]));
        }
        m0 = fmaxf(m0, __shfl_xor_sync(0xffffffffu, m0, 1));
        m0 = fmaxf(m0, __shfl_xor_sync(0xffffffffu, m0, 2));
        m1 = fmaxf(m1, __shfl_xor_sync(0xffffffffu, m1, 1));
        m1 = fmaxf(m1, __shfl_xor_sync(0xffffffffu, m1, 2));

        float s0 = 0.f, s1 = 0.f;
        #pragma unroll
        for (int nt = 0; nt < NT; nt++) {
            sacc[nt][0] = __expf(sacc[nt][0] - m0);
            sacc[nt][1] = __expf(sacc[nt][1] - m0);
            sacc[nt][2] = __expf(sacc[nt][2] - m1);
            sacc[nt][3] = __expf(sacc[nt][3] - m1);
            s0 += sacc[nt][0] + sacc[nt][1];
            s1 += sacc[nt][2] + sacc[nt][3];
        }
        s0 += __shfl_xor_sync(0xffffffffu, s0, 1);
        s0 += __shfl_xor_sync(0xffffffffu, s0, 2);
        s1 += __shfl_xor_sync(0xffffffffu, s1, 1);
        s1 += __shfl_xor_sync(0xffffffffu, s1, 2);
        float rinv0 = 1.f / s0;
        float rinv1 = 1.f / s1;

        uint32_t pa[KT2][4];
        #pragma unroll
        for (int kt = 0; kt < KT2; kt++) {
            int nt0 = 2 * kt, nt1 = 2 * kt + 1;
            pa[kt][0] = pack_h2(sacc[nt0][0], sacc[nt0][1]);
            pa[kt][1] = pack_h2(sacc[nt0][2], sacc[nt0][3]);
            pa[kt][2] = pack_h2(sacc[nt1][0], sacc[nt1][1]);
            pa[kt][3] = pack_h2(sacc[nt1][2], sacc[nt1][3]);
        }

        float oacc[4][4];
        #pragma unroll
        for (int dt = 0; dt < 4; dt++)
            #pragma unroll
            for (int e = 0; e < 4; e++) oacc[dt][e] = 0.f;

        #pragma unroll
        for (int kt = 0; kt < KT2; kt++) {
            #pragma unroll
            for (int dt = 0; dt < 4; dt++) {
                uint32_t bv[2];
                bv[0] = Vp[hh][8 * kt + c][dt * 8 + r];
                bv[1] = Vp[hh][8 * kt + c + 4][dt * 8 + r];
                mma_f16(oacc[dt], pa[kt], bv);
            }
        }

        int row0 = q0 + r;
        int row1 = q0 + 8 + r;
        #pragma unroll
        for (int dt = 0; dt < 4; dt++) {
            if (row0 < S) {
                uint32_t o = pack_h2(oacc[dt][0] * rinv0, oacc[dt][1] * rinv0);
                *(uint32_t*)&att[(size_t)(nb + cs * row0) * DD + hcur * HD + dt * 8 + 2 * c] = o;
            }
            if (row1 < S) {
                uint32_t o = pack_h2(oacc[dt][2] * rinv1, oacc[dt][3] * rinv1);
                *(uint32_t*)&att[(size_t)(nb + cs * row1) * DD + hcur * HD + dt * 8 + 2 * c] = o;
            }
        }
    }
}

// ---------------------------------------------------------------------------
// Host launcher
// ---------------------------------------------------------------------------
extern "C" void kernel_launch(void* const* d_in, const int* in_sizes, int n_in,
                              void* d_out, int out_size)
{
    const float* x         = (const float*)d_in[0];
    const float* lat_grid  = (const float*)d_in[1];
    const float* lon_grid  = (const float*)d_in[2];
    const float* lat_qkv_w = (const float*)d_in[3];
    const float* lat_qkv_b = (const float*)d_in[4];
    const float* lon_qkv_w = (const float*)d_in[5];
    const float* lon_qkv_b = (const float*)d_in[6];
    const float* lev_qkv_w = (const float*)d_in[7];
    const float* lev_qkv_b = (const float*)d_in[8];
    const float* proj_w    = (const float*)d_in[9];
    const float* proj_b    = (const float*)d_in[10];
    const float* g_lat     = (const float*)d_in[11];
    const float* b_lat     = (const float*)d_in[12];
    const float* g_lon     = (const float*)d_in[13];
    const float* b_lon     = (const float*)d_in[14];
    const float* g_lev     = (const float*)d_in[15];
    const float* b_lev     = (const float*)d_in[16];
    float* out = (float*)d_out;

    __half *lnh, *qkvh, *atth, *stateh;
    float *slat, *clat, *slon, *clon;
    uint32_t *wpq, *wpp;
    cudaGetSymbolAddress((void**)&lnh,    g_lnh);
    cudaGetSymbolAddress((void**)&qkvh,   g_qkvh);
    cudaGetSymbolAddress((void**)&atth,   g_atth);
    cudaGetSymbolAddress((void**)&stateh, g_stateh);
    cudaGetSymbolAddress((void**)&slat,   g_sin_lat);
    cudaGetSymbolAddress((void**)&clat,   g_cos_lat);
    cudaGetSymbolAddress((void**)&slon,   g_sin_lon);
    cudaGetSymbolAddress((void**)&clon,   g_cos_lon);
    cudaGetSymbolAddress((void**)&wpq,    g_wp_qkv);
    cudaGetSymbolAddress((void**)&wpp,    g_wp_proj);

    uint32_t* wp_lat = wpq;
    uint32_t* wp_lon = wpq + (size_t)(DD / 2) * 3 * DD;
    uint32_t* wp_lev = wpq + (size_t)2 * (DD / 2) * 3 * DD;

    pack_w_kernel<<<dim3(3 * DD / 256, DD / 2), 256>>>(lat_qkv_w, wp_lat, DD, 3 * DD);
    pack_w_kernel<<<dim3(3 * DD / 256, DD / 2), 256>>>(lon_qkv_w, wp_lon, DD, 3 * DD);
    pack_w_kernel<<<dim3(3 * DD / 256, DD / 2), 256>>>(lev_qkv_w, wp_lev, DD, 3 * DD);
    pack_w_kernel<<<dim3(DD / 256, DD / 2), 256>>>(proj_w, wpp, DD, DD);

    rotary_kernel<<<(HH * 16 + 127) / 128, 128>>>(lat_grid, HH, 0, slat, clat);
    rotary_kernel<<<(WW * 16 + 127) / 128, 128>>>(lon_grid, WW, 1, slon, clon);

    dim3 gq(3 * DD / 128, TT / 128);   // (12, 468)
    dim3 gp(DD / 128, TT / 128);       // (4, 468)

    // ---- lat block (seq = H, n over (l,w)): residual = x (fp32) -> f16 state
    ln_kernel<float><<<TT / 8, 256>>>(x, g_lat, b_lat, lnh);
    gemm_f16_kernel<__half, float><<<gq, 128>>>(lnh, wp_lat, lat_qkv_b, (const float*)nullptr, qkvh, TT, 3 * DD, DD);
    attn_mma_kernel<HH, 1><<<dim3(LL * WW, NHEAD), 128>>>(qkvh, atth, slat, clat,
                                                          WW, HH * WW, 1, WW);
    gemm_f16_kernel<__half, float><<<gp, 128>>>(atth, wpp, proj_b, x, stateh, TT, DD, DD);

    // ---- lon block (seq = W, n over (l,h)): f16 residual in/out (in-place)
    ln_kernel<__half><<<TT / 8, 256>>>(stateh, g_lon, b_lon, lnh);
    gemm_f16_kernel<__half, float><<<gq, 128>>>(lnh, wp_lon, lon_qkv_b, (const float*)nullptr, qkvh, TT, 3 * DD, DD);
    attn_mma_kernel<WW, 1><<<dim3(LL * HH, NHEAD), 128>>>(qkvh, atth, slon, clon,
                                                          1, WW, 0, 1);
    gemm_f16_kernel<__half, __half><<<gp, 128>>>(atth, wpp, proj_b, stateh, stateh, TT, DD, DD);

    // ---- lev block (seq = L, n over (h,w), no rotary): final out fp32
    ln_kernel<__half><<<TT / 8, 256>>>(stateh, g_lev, b_lev, lnh);
    gemm_f16_kernel<__half, float><<<gq, 128>>>(lnh, wp_lev, lev_qkv_b, (const float*)nullptr, qkvh, TT, 3 * DD, DD);
    attn_mma_kernel<LL, 4><<<dim3(HH * WW, NHEAD / 4), 128>>>(qkvh, atth, nullptr, nullptr,
                                                              1, 1, 0, HH * WW);
    gemm_f16_kernel<float, __half><<<gp, 128>>>(atth, wpp, proj_b, stateh, out, TT, DD, DD);
}

// round 16
// speedup vs baseline: 1.1283x; 1.0423x over previous
#include <cuda_runtime.h>
#include <cuda_bf16.h>
#include <cuda_fp16.h>
#include <math.h>
#include <stdint.h>

// Problem constants
#define LL 13
#define HH 48
#define WW 96
#define DD 512
#define TT (LL*HH*WW)        // 59904 tokens
#define NHEAD 16
#define HD 32

// Scratch (device globals; no cudaMalloc allowed)
__device__ __half g_lnh[(size_t)TT * DD];          // LN output (GEMM A), f16
__device__ __half g_qkvh[(size_t)TT * 3 * DD];     // QKV output, f16
__device__ __half g_atth[(size_t)TT * DD];         // attention output (proj A), f16
__device__ __half g_stateh[(size_t)TT * DD];       // residual stream, f16
__device__ float  g_sin_lat[HH * 16];
__device__ float  g_cos_lat[HH * 16];
__device__ float  g_sin_lon[WW * 16];
__device__ float  g_cos_lon[WW * 16];
__device__ uint32_t g_wp_qkv[3][(DD / 2) * 3 * DD];  // packed f16 weights [K/2][N]
__device__ uint32_t g_wp_proj[(DD / 2) * DD];

// ---------------------------------------------------------------------------
// MMA + helpers
// ---------------------------------------------------------------------------
__device__ __forceinline__ void mma_f16(float* d, const uint32_t* a, const uint32_t* b)
{
    asm volatile(
        "mma.sync.aligned.m16n8k16.row.col.f32.f16.f16.f32 "
        "{%0,%1,%2,%3}, {%4,%5,%6,%7}, {%8,%9}, {%0,%1,%2,%3};"
        : "+f"(d[0]), "+f"(d[1]), "+f"(d[2]), "+f"(d[3])
        : "r"(a[0]), "r"(a[1]), "r"(a[2]), "r"(a[3]), "r"(b[0]), "r"(b[1]));
}

__device__ __forceinline__ uint32_t pack_h2(float lo, float hi)
{
    __half2 t = __floats2half2_rn(lo, hi);
    return *(uint32_t*)&t;
}

__device__ __forceinline__ float2 unpack_h2(uint32_t w)
{
    __half2 t = *(__half2*)&w;
    return __half22float2(t);
}

__device__ __forceinline__ void cp_async16(uint32_t dst, const void* src)
{
    asm volatile("cp.async.cg.shared.global [%0], [%1], 16;\n" :: "r"(dst), "l"(src));
}
__device__ __forceinline__ void cp_commit()
{
    asm volatile("cp.async.commit_group;\n" ::: "memory");
}
__device__ __forceinline__ void cp_wait0()
{
    asm volatile("cp.async.wait_group 0;\n" ::: "memory");
}

// ---------------------------------------------------------------------------
// Weight pack: W[K][N] fp32 -> out[k2][n] = half2(W[2k2][n], W[2k2+1][n])
// ---------------------------------------------------------------------------
__global__ void pack_w_kernel(const float* __restrict__ W, uint32_t* __restrict__ out,
                              int K, int N)
{
    int n  = blockIdx.x * 256 + threadIdx.x;
    int k2 = blockIdx.y;
    if (n < N)
        out[(size_t)k2 * N + n] =
            pack_h2(W[(size_t)(2 * k2) * N + n], W[(size_t)(2 * k2 + 1) * N + n]);
}

// ---------------------------------------------------------------------------
// Rotary sin/cos precompute. mode 0: lat axis (lon=0), mode 1: lon axis (lat=0)
// ---------------------------------------------------------------------------
__global__ void rotary_kernel(const float* __restrict__ grid, int S, int mode,
                              float* __restrict__ sout, float* __restrict__ cout)
{
    int idx = blockIdx.x * blockDim.x + threadIdx.x;
    if (idx >= S * 16) return;
    int s = idx >> 4;
    int f = idx & 15;
    const float PI = 3.14159265358979323846f;
    float lat, lon;
    if (mode == 0) { lat = grid[s]; lon = 0.f; }
    else           { lat = 0.f;     lon = grid[s]; }
    float two_pi = 2.f * PI;
    float r = fmodf(lon + PI, two_pi);
    if (r < 0.f) r += two_pi;
    float lonw = r - PI;
    float lo = -(PI * 0.5f) + 1e-6f;
    float hi =  (PI * 0.5f) - 1e-6f;
    float latc = fminf(fmaxf(lat, lo), hi);
    float invf = powf(10000.f, -(float)f / 16.f);
    float phase = (latc + lonw * cosf(latc)) * invf;
    sout[idx] = sinf(phase);
    cout[idx] = cosf(phase);
}

// ---------------------------------------------------------------------------
// LayerNorm, warp-per-token (no smem/barriers). 256 thr = 8 tokens.
// InT: float or __half.
// ---------------------------------------------------------------------------
template<typename InT>
__global__ void ln_kernel(const InT* __restrict__ x, const float* __restrict__ g,
                          const float* __restrict__ b, __half* __restrict__ out)
{
    int warp = threadIdx.x >> 5, lane = threadIdx.x & 31;
    int t = blockIdx.x * 8 + warp;
    const InT* row = x + (size_t)t * DD;

    float4 v[4];
    float s = 0.f, q = 0.f;
    #pragma unroll
    for (int k = 0; k < 4; k++) {
        if constexpr (sizeof(InT) == 2) {
            uint2 w = *(const uint2*)(row + lane * 4 + 128 * k);
            float2 lo = unpack_h2(w.x);
            float2 hi = unpack_h2(w.y);
            v[k] = make_float4(lo.x, lo.y, hi.x, hi.y);
        } else {
            v[k] = *(const float4*)(row + lane * 4 + 128 * k);
        }
        s += v[k].x + v[k].y + v[k].z + v[k].w;
        q += v[k].x*v[k].x + v[k].y*v[k].y + v[k].z*v[k].z + v[k].w*v[k].w;
    }
    #pragma unroll
    for (int o = 16; o; o >>= 1) {
        s += __shfl_xor_sync(0xffffffffu, s, o);
        q += __shfl_xor_sync(0xffffffffu, q, o);
    }
    float mean = s * (1.f / 512.f);
    float var  = q * (1.f / 512.f) - mean * mean;
    float inv = rsqrtf(var + 1e-5f);

    #pragma unroll
    for (int k = 0; k < 4; k++) {
        float4 gv = *(const float4*)(g + lane * 4 + 128 * k);
        float4 bv = *(const float4*)(b + lane * 4 + 128 * k);
        uint2 o;
        o.x = pack_h2((v[k].x - mean) * inv * gv.x + bv.x,
                      (v[k].y - mean) * inv * gv.y + bv.y);
        o.y = pack_h2((v[k].z - mean) * inv * gv.z + bv.z,
                      (v[k].w - mean) * inv * gv.w + bv.w);
        *(uint2*)(out + (size_t)t * DD + lane * 4 + 128 * k) = o;
    }
}

// ---------------------------------------------------------------------------
// F16 tensor-core GEMM: C = A@B + bias (+ res). OutT/ResT: float or __half.
// Block 128x128, 4 warps @64x64, BK=32, 2-stage cp.async, one sync per chunk.
// __launch_bounds__(128, 3): cap 170 regs -> 3 CTAs/SM for latency hiding.
// bfrag loaded per-j inside the loop to keep the live set under the cap.
// ---------------------------------------------------------------------------
__device__ __forceinline__ void gemm_issue_chunk(
    const __half* __restrict__ A, const uint32_t* __restrict__ Bp,
    int N, int K, int m0, int n0, int tid,
    uint32_t as_base, uint32_t bs_base,
    int chunk, int buf)
{
    int k0 = chunk * 32;
    int arow = tid >> 2;
    int aq   = tid & 3;
    #pragma unroll
    for (int i = 0; i < 4; i++) {
        int row = arow + 32 * i;
        uint32_t dst = as_base + (uint32_t)(((buf * 128 + row) * 20 + aq * 4) * 4);
        cp_async16(dst, A + (size_t)(m0 + row) * K + k0 + aq * 8);
    }
    int bk = tid >> 5;
    int bt = tid & 31;
    #pragma unroll
    for (int i = 0; i < 4; i++) {
        int krow = bk + 4 * i;
        uint32_t dst = bs_base + (uint32_t)(((buf * 16 + krow) * 136 + bt * 4) * 4);
        cp_async16(dst, Bp + (size_t)(k0 / 2 + krow) * N + n0 + bt * 4);
    }
    cp_commit();
}

template<typename OutT, typename ResT>
__global__ __launch_bounds__(128, 3) void gemm_f16_kernel(
    const __half* __restrict__ A, const uint32_t* __restrict__ Bp,
    const float* __restrict__ bias, const ResT* __restrict__ res,
    OutT* __restrict__ C, int M, int N, int K)
{
    __shared__ uint32_t Au[2][128][20];
    __shared__ uint32_t Bu[2][16][136];

    int tid  = threadIdx.x;
    int lane = tid & 31;
    int warp = tid >> 5;
    int wm   = warp >> 1;
    int wn   = warp & 1;
    int r    = lane >> 2;
    int c    = lane & 3;

    int m0 = blockIdx.y * 128;
    int n0 = blockIdx.x * 128;

    uint32_t as_base = (uint32_t)__cvta_generic_to_shared(&Au[0][0][0]);
    uint32_t bs_base = (uint32_t)__cvta_generic_to_shared(&Bu[0][0][0]);

    float acc[4][8][4];
    #pragma unroll
    for (int i = 0; i < 4; i++)
        #pragma unroll
        for (int j = 0; j < 8; j++)
            #pragma unroll
            for (int e = 0; e < 4; e++) acc[i][j][e] = 0.f;

    const int NCHUNK = K / 32;

    gemm_issue_chunk(A, Bp, N, K, m0, n0, tid, as_base, bs_base, 0, 0);

    for (int chunk = 0; chunk < NCHUNK; chunk++) {
        int buf = chunk & 1;
        cp_wait0();
        __syncthreads();   // data ready + all warps done reading buf (prev iter)

        if (chunk + 1 < NCHUNK)
            gemm_issue_chunk(A, Bp, N, K, m0, n0, tid,
                             as_base, bs_base, chunk + 1, buf ^ 1);

        #pragma unroll
        for (int ks = 0; ks < 2; ks++) {
            int kb = ks * 8;
            uint32_t afrag[4][4];
            #pragma unroll
            for (int i = 0; i < 4; i++) {
                int row = wm * 64 + i * 16 + r;
                afrag[i][0] = Au[buf][row][kb + c];
                afrag[i][1] = Au[buf][row + 8][kb + c];
                afrag[i][2] = Au[buf][row][kb + c + 4];
                afrag[i][3] = Au[buf][row + 8][kb + c + 4];
            }
            #pragma unroll
            for (int j = 0; j < 8; j++) {
                int col = wn * 64 + j * 8 + r;
                uint32_t bfrag[2];
                bfrag[0] = Bu[buf][kb + c][col];
                bfrag[1] = Bu[buf][kb + c + 4][col];
                #pragma unroll
                for (int i = 0; i < 4; i++)
                    mma_f16(acc[i][j], afrag[i], bfrag);
            }
        }
        // no trailing sync — next iteration's post-wait sync protects buf
    }

    #pragma unroll
    for (int i = 0; i < 4; i++) {
        int row0 = m0 + wm * 64 + i * 16 + r;
        #pragma unroll
        for (int j = 0; j < 8; j++) {
            int col = n0 + wn * 64 + j * 8 + 2 * c;
            float bv0 = bias[col];
            float bv1 = bias[col + 1];
            size_t idx0 = (size_t)row0 * N + col;
            size_t idx1 = (size_t)(row0 + 8) * N + col;
            float o00 = acc[i][j][0] + bv0, o01 = acc[i][j][1] + bv1;
            float o10 = acc[i][j][2] + bv0, o11 = acc[i][j][3] + bv1;
            if (res) {
                if constexpr (sizeof(ResT) == 2) {
                    float2 r0 = unpack_h2(*(const uint32_t*)(res + idx0));
                    float2 r1 = unpack_h2(*(const uint32_t*)(res + idx1));
                    o00 += r0.x; o01 += r0.y;
                    o10 += r1.x; o11 += r1.y;
                } else {
                    const float2 r0 = *(const float2*)(res + idx0);
                    const float2 r1 = *(const float2*)(res + idx1);
                    o00 += r0.x; o01 += r0.y;
                    o10 += r1.x; o11 += r1.y;
                }
            }
            if constexpr (sizeof(OutT) == 2) {
                *(uint32_t*)(C + idx0) = pack_h2(o00, o01);
                *(uint32_t*)(C + idx1) = pack_h2(o10, o11);
            } else {
                *(float2*)(C + idx0) = make_float2(o00, o01);
                *(float2*)(C + idx1) = make_float2(o10, o11);
            }
        }
    }
}

// ---------------------------------------------------------------------------
// Full-f16 tensor-core attention, HPB heads per block (HPB=1 lat/lon, 4 lev).
// flat(n,s) = cd*(n/d0) + cm*(n%d0) + cs*s
// ---------------------------------------------------------------------------
template<int S, int HPB>
__global__ __launch_bounds__(128) void attn_mma_kernel(
    const __half* __restrict__ qkv, __half* __restrict__ att,
    const float* __restrict__ rsin, const float* __restrict__ rcos,
    int d0, int cd, int cm, int cs)
{
    constexpr int NT    = (S + 7) / 8;
    constexpr int QT    = (S + 15) / 16;
    constexpr int KT2   = NT / 2;
    constexpr int NT8   = NT * 8;
    constexpr int D8    = (8 - (NT8 % 32) + 32) % 32;
    constexpr int D24   = (24 - (NT8 % 32) + 32) % 32;
    constexpr int KSTR2 = NT8 + (D8 < D24 ? D8 : D24);
    constexpr int QROWS = QT * 16;

    __shared__ uint32_t Qp[HPB][QROWS][20];
    __shared__ uint32_t Ktp[HPB][16][KSTR2];
    __shared__ uint32_t Vp[HPB][NT * 4][40];

    int n = blockIdx.x;
    int hg0 = blockIdx.y * HPB;
    int tid = threadIdx.x;
    int lane = tid & 31;
    int warp = tid >> 5;
    int r = lane >> 2;
    int c = lane & 3;

    int nb = cd * (n / d0) + cm * (n % d0);
    const float scale = 0.17677669529663687f;

    for (int idx = tid; idx < HPB * QROWS * 16; idx += 128) {
        int p = idx & 15;
        int j = (idx >> 4) % QROWS;
        int hh = (idx >> 4) / QROWS;
        uint32_t w = 0;
        if (j < S) {
            size_t rowb = (size_t)(nb + cs * j) * (3 * DD) + (hg0 + hh) * HD;
            float f0, f1;
            if (rsin) {
                if (p < 8) {
                    int d0i = 2 * p, d1i = 2 * p + 1;
                    f0 = __half2float(qkv[rowb + 2 * d0i]) * rcos[j * 16 + d0i]
                       - __half2float(qkv[rowb + 2 * d0i + 1]) * rsin[j * 16 + d0i];
                    f1 = __half2float(qkv[rowb + 2 * d1i]) * rcos[j * 16 + d1i]
                       - __half2float(qkv[rowb + 2 * d1i + 1]) * rsin[j * 16 + d1i];
                } else {
                    int i0 = 2 * p - 16, i1 = 2 * p - 15;
                    f0 = __half2float(qkv[rowb + 2 * i0]) * rsin[j * 16 + i0]
                       + __half2float(qkv[rowb + 2 * i0 + 1]) * rcos[j * 16 + i0];
                    f1 = __half2float(qkv[rowb + 2 * i1]) * rsin[j * 16 + i1]
                       + __half2float(qkv[rowb + 2 * i1 + 1]) * rcos[j * 16 + i1];
                }
            } else {
                f0 = __half2float(qkv[rowb + 2 * p]);
                f1 = __half2float(qkv[rowb + 2 * p + 1]);
            }
            w = pack_h2(f0 * scale, f1 * scale);
        }
        Qp[hh][j][p] = w;
    }
    for (int idx = tid; idx < HPB * NT8 * 16; idx += 128) {
        int p = idx & 15;
        int j = (idx >> 4) % NT8;
        int hh = (idx >> 4) / NT8;
        uint32_t w = 0;
        if (j < S) {
            size_t rowb = (size_t)(nb + cs * j) * (3 * DD) + DD + (hg0 + hh) * HD;
            float f0, f1;
            if (rsin) {
                if (p < 8) {
                    int d0i = 2 * p, d1i = 2 * p + 1;
                    f0 = __half2float(qkv[rowb + 2 * d0i]) * rcos[j * 16 + d0i]
                       - __half2float(qkv[rowb + 2 * d0i + 1]) * rsin[j * 16 + d0i];
                    f1 = __half2float(qkv[rowb + 2 * d1i]) * rcos[j * 16 + d1i]
                       - __half2float(qkv[rowb + 2 * d1i + 1]) * rsin[j * 16 + d1i];
                } else {
                    int i0 = 2 * p - 16, i1 = 2 * p - 15;
                    f0 = __half2float(qkv[rowb + 2 * i0]) * rsin[j * 16 + i0]
                       + __half2float(qkv[rowb + 2 * i0 + 1]) * rcos[j * 16 + i0];
                    f1 = __half2float(qkv[rowb + 2 * i1]) * rsin[j * 16 + i1]
                       + __half2float(qkv[rowb + 2 * i1 + 1]) * rcos[j * 16 + i1];
                }
                w = pack_h2(f0, f1);
            } else {
                __half h0 = qkv[rowb + 2 * p];
                __half h1 = qkv[rowb + 2 * p + 1];
                __half2 t = __halves2half2(h0, h1);
                w = *(uint32_t*)&t;
            }
        }
        Ktp[hh][p][j] = w;
    }
    for (int idx = tid; idx < HPB * NT * 4 * 32; idx += 128) {
        int d = idx & 31;
        int j2 = (idx >> 5) % (NT * 4);
        int hh = (idx >> 5) / (NT * 4);
        int j0 = 2 * j2, j1 = 2 * j2 + 1;
        size_t voff = 2 * DD + (hg0 + hh) * HD;
        __half v0 = (j0 < S) ? qkv[(size_t)(nb + cs * j0) * (3 * DD) + voff + d] : __half(0.f);
        __half v1 = (j1 < S) ? qkv[(size_t)(nb + cs * j1) * (3 * DD) + voff + d] : __half(0.f);
        __half2 t = __halves2half2(v0, v1);
        Vp[hh][j2][d] = *(uint32_t*)&t;
    }
    __syncthreads();

    for (int t = warp; t < HPB * QT; t += 4) {
        int hh = t / QT;
        int qt = t % QT;
        int q0 = qt * 16;
        int hcur = hg0 + hh;

        uint32_t aq[2][4];
        #pragma unroll
        for (int s = 0; s < 2; s++) {
            aq[s][0] = Qp[hh][q0 + r][8 * s + c];
            aq[s][1] = Qp[hh][q0 + 8 + r][8 * s + c];
            aq[s][2] = Qp[hh][q0 + r][8 * s + c + 4];
            aq[s][3] = Qp[hh][q0 + 8 + r][8 * s + c + 4];
        }

        float sacc[NT][4];
        #pragma unroll
        for (int nt = 0; nt < NT; nt++)
            #pragma unroll
            for (int e = 0; e < 4; e++) sacc[nt][e] = 0.f;

        #pragma unroll
        for (int nt = 0; nt < NT; nt++) {
            #pragma unroll
            for (int s = 0; s < 2; s++) {
                uint32_t bk[2];
                bk[0] = Ktp[hh][8 * s + c][nt * 8 + r];
                bk[1] = Ktp[hh][8 * s + c + 4][nt * 8 + r];
                mma_f16(sacc[nt], aq[s], bk);
            }
        }

        #pragma unroll
        for (int nt = 0; nt < NT; nt++) {
            int col = nt * 8 + 2 * c;
            if (col >= S)     { sacc[nt][0] = -1e30f; sacc[nt][2] = -1e30f; }
            if (col + 1 >= S) { sacc[nt][1] = -1e30f; sacc[nt][3] = -1e30f; }
        }

        float m0 = -1e30f, m1 = -1e30f;
        #pragma unroll
        for (int nt = 0; nt < NT; nt++) {
            m0 = fmaxf(m0, fmaxf(sacc[nt][0], sacc[nt][1]));
            m1 = fmaxf(m1, fmaxf(sacc[nt][2], sacc[nt][3]));
        }
        m0 = fmaxf(m0, __shfl_xor_sync(0xffffffffu, m0, 1));
        m0 = fmaxf(m0, __shfl_xor_sync(0xffffffffu, m0, 2));
        m1 = fmaxf(m1, __shfl_xor_sync(0xffffffffu, m1, 1));
        m1 = fmaxf(m1, __shfl_xor_sync(0xffffffffu, m1, 2));

        float s0 = 0.f, s1 = 0.f;
        #pragma unroll
        for (int nt = 0; nt < NT; nt++) {
            sacc[nt][0] = __expf(sacc[nt][0] - m0);
            sacc[nt][1] = __expf(sacc[nt][1] - m0);
            sacc[nt][2] = __expf(sacc[nt][2] - m1);
            sacc[nt][3] = __expf(sacc[nt][3] - m1);
            s0 += sacc[nt][0] + sacc[nt][1];
            s1 += sacc[nt][2] + sacc[nt][3];
        }
        s0 += __shfl_xor_sync(0xffffffffu, s0, 1);
        s0 += __shfl_xor_sync(0xffffffffu, s0, 2);
        s1 += __shfl_xor_sync(0xffffffffu, s1, 1);
        s1 += __shfl_xor_sync(0xffffffffu, s1, 2);
        float rinv0 = 1.f / s0;
        float rinv1 = 1.f / s1;

        uint32_t pa[KT2][4];
        #pragma unroll
        for (int kt = 0; kt < KT2; kt++) {
            int nt0 = 2 * kt, nt1 = 2 * kt + 1;
            pa[kt][0] = pack_h2(sacc[nt0][0], sacc[nt0][1]);
            pa[kt][1] = pack_h2(sacc[nt0][2], sacc[nt0][3]);
            pa[kt][2] = pack_h2(sacc[nt1][0], sacc[nt1][1]);
            pa[kt][3] = pack_h2(sacc[nt1][2], sacc[nt1][3]);
        }

        float oacc[4][4];
        #pragma unroll
        for (int dt = 0; dt < 4; dt++)
            #pragma unroll
            for (int e = 0; e < 4; e++) oacc[dt][e] = 0.f;

        #pragma unroll
        for (int kt = 0; kt < KT2; kt++) {
            #pragma unroll
            for (int dt = 0; dt < 4; dt++) {
                uint32_t bv[2];
                bv[0] = Vp[hh][8 * kt + c][dt * 8 + r];
                bv[1] = Vp[hh][8 * kt + c + 4][dt * 8 + r];
                mma_f16(oacc[dt], pa[kt], bv);
            }
        }

        int row0 = q0 + r;
        int row1 = q0 + 8 + r;
        #pragma unroll
        for (int dt = 0; dt < 4; dt++) {
            if (row0 < S) {
                uint32_t o = pack_h2(oacc[dt][0] * rinv0, oacc[dt][1] * rinv0);
                *(uint32_t*)&att[(size_t)(nb + cs * row0) * DD + hcur * HD + dt * 8 + 2 * c] = o;
            }
            if (row1 < S) {
                uint32_t o = pack_h2(oacc[dt][2] * rinv1, oacc[dt][3] * rinv1);
                *(uint32_t*)&att[(size_t)(nb + cs * row1) * DD + hcur * HD + dt * 8 + 2 * c] = o;
            }
        }
    }
}

// ---------------------------------------------------------------------------
// Host launcher
// ---------------------------------------------------------------------------
extern "C" void kernel_launch(void* const* d_in, const int* in_sizes, int n_in,
                              void* d_out, int out_size)
{
    const float* x         = (const float*)d_in[0];
    const float* lat_grid  = (const float*)d_in[1];
    const float* lon_grid  = (const float*)d_in[2];
    const float* lat_qkv_w = (const float*)d_in[3];
    const float* lat_qkv_b = (const float*)d_in[4];
    const float* lon_qkv_w = (const float*)d_in[5];
    const float* lon_qkv_b = (const float*)d_in[6];
    const float* lev_qkv_w = (const float*)d_in[7];
    const float* lev_qkv_b = (const float*)d_in[8];
    const float* proj_w    = (const float*)d_in[9];
    const float* proj_b    = (const float*)d_in[10];
    const float* g_lat     = (const float*)d_in[11];
    const float* b_lat     = (const float*)d_in[12];
    const float* g_lon     = (const float*)d_in[13];
    const float* b_lon     = (const float*)d_in[14];
    const float* g_lev     = (const float*)d_in[15];
    const float* b_lev     = (const float*)d_in[16];
    float* out = (float*)d_out;

    __half *lnh, *qkvh, *atth, *stateh;
    float *slat, *clat, *slon, *clon;
    uint32_t *wpq, *wpp;
    cudaGetSymbolAddress((void**)&lnh,    g_lnh);
    cudaGetSymbolAddress((void**)&qkvh,   g_qkvh);
    cudaGetSymbolAddress((void**)&atth,   g_atth);
    cudaGetSymbolAddress((void**)&stateh, g_stateh);
    cudaGetSymbolAddress((void**)&slat,   g_sin_lat);
    cudaGetSymbolAddress((void**)&clat,   g_cos_lat);
    cudaGetSymbolAddress((void**)&slon,   g_sin_lon);
    cudaGetSymbolAddress((void**)&clon,   g_cos_lon);
    cudaGetSymbolAddress((void**)&wpq,    g_wp_qkv);
    cudaGetSymbolAddress((void**)&wpp,    g_wp_proj);

    uint32_t* wp_lat = wpq;
    uint32_t* wp_lon = wpq + (size_t)(DD / 2) * 3 * DD;
    uint32_t* wp_lev = wpq + (size_t)2 * (DD / 2) * 3 * DD;

    pack_w_kernel<<<dim3(3 * DD / 256, DD / 2), 256>>>(lat_qkv_w, wp_lat, DD, 3 * DD);
    pack_w_kernel<<<dim3(3 * DD / 256, DD / 2), 256>>>(lon_qkv_w, wp_lon, DD, 3 * DD);
    pack_w_kernel<<<dim3(3 * DD / 256, DD / 2), 256>>>(lev_qkv_w, wp_lev, DD, 3 * DD);
    pack_w_kernel<<<dim3(DD / 256, DD / 2), 256>>>(proj_w, wpp, DD, DD);

    rotary_kernel<<<(HH * 16 + 127) / 128, 128>>>(lat_grid, HH, 0, slat, clat);
    rotary_kernel<<<(WW * 16 + 127) / 128, 128>>>(lon_grid, WW, 1, slon, clon);

    dim3 gq(3 * DD / 128, TT / 128);   // (12, 468)
    dim3 gp(DD / 128, TT / 128);       // (4, 468)

    // ---- lat block (seq = H, n over (l,w)): residual = x (fp32) -> f16 state
    ln_kernel<float><<<TT / 8, 256>>>(x, g_lat, b_lat, lnh);
    gemm_f16_kernel<__half, float><<<gq, 128>>>(lnh, wp_lat, lat_qkv_b, (const float*)nullptr, qkvh, TT, 3 * DD, DD);
    attn_mma_kernel<HH, 1><<<dim3(LL * WW, NHEAD), 128>>>(qkvh, atth, slat, clat,
                                                          WW, HH * WW, 1, WW);
    gemm_f16_kernel<__half, float><<<gp, 128>>>(atth, wpp, proj_b, x, stateh, TT, DD, DD);

    // ---- lon block (seq = W, n over (l,h)): f16 residual in/out (in-place)
    ln_kernel<__half><<<TT / 8, 256>>>(stateh, g_lon, b_lon, lnh);
    gemm_f16_kernel<__half, float><<<gq, 128>>>(lnh, wp_lon, lon_qkv_b, (const float*)nullptr, qkvh, TT, 3 * DD, DD);
    attn_mma_kernel<WW, 1><<<dim3(LL * HH, NHEAD), 128>>>(qkvh, atth, slon, clon,
                                                          1, WW, 0, 1);
    gemm_f16_kernel<__half, __half><<<gp, 128>>>(atth, wpp, proj_b, stateh, stateh, TT, DD, DD);

    // ---- lev block (seq = L, n over (h,w), no rotary): final out fp32
    ln_kernel<__half><<<TT / 8, 256>>>(stateh, g_lev, b_lev, lnh);
    gemm_f16_kernel<__half, float><<<gq, 128>>>(lnh, wp_lev, lev_qkv_b, (const float*)nullptr, qkvh, TT, 3 * DD, DD);
    attn_mma_kernel<LL, 4><<<dim3(HH * WW, NHEAD / 4), 128>>>(qkvh, atth, nullptr, nullptr,
                                                              1, 1, 0, HH * WW);
    gemm_f16_kernel<float, __half><<<gp, 128>>>(atth, wpp, proj_b, stateh, out, TT, DD, DD);
}